// round 6
// baseline (speedup 1.0000x reference)
#include <cuda_runtime.h>
#include <math.h>
#include <stdint.h>

#define NB 48
#define NC 768
#define NS 361
#define NT 64
#define SPAD 384
#define NPAIR (NB * NB)

#define TEMP1 4.0f
#define TEMP2 5.0f
#define TEMP3 10.0f
#define EPSV  1e-8f

typedef unsigned long long ull;

// ----- device scratch -----
__device__ float g_ctxp[(size_t)NB * NC * SPAD];     // padded ctx [b][d][384]
__device__ float g_G[(size_t)NB * SPAD * SPAD];      // padded Gram [b][384][384]
__device__ float g_a2u[(size_t)NPAIR * SPAD * NT];   // unnorm a2 per pair (~226MB)
__device__ float g_cols[NPAIR * NT];
__device__ float g_w12[NPAIR * NT];
__device__ float g_w2[NPAIR * NT];
__device__ float g_w1n[NB * NT];
__device__ float g_gn[NB];
__device__ float g_sn[NB];
__device__ float g_sc0[NB * NB];
__device__ float g_sims[NB * NB];

// ----- tf32 helpers -----
__device__ __forceinline__ uint32_t f2tf(float v) {
    uint32_t r;
    asm("cvt.rna.tf32.f32 %0, %1;" : "=r"(r) : "f"(v));
    return r;
}
__device__ __forceinline__ void mma8(float* c, uint32_t a0, uint32_t a1,
                                     uint32_t a2, uint32_t a3,
                                     uint32_t b0, uint32_t b1) {
    asm volatile(
        "mma.sync.aligned.m16n8k8.row.col.f32.tf32.tf32.f32 "
        "{%0,%1,%2,%3}, {%4,%5,%6,%7}, {%8,%9}, {%0,%1,%2,%3};"
        : "+f"(c[0]), "+f"(c[1]), "+f"(c[2]), "+f"(c[3])
        : "r"(a0), "r"(a1), "r"(a2), "r"(a3), "r"(b0), "r"(b1));
}
__device__ __forceinline__ void split4(float* hi, float* lo, int o, float4 v) {
    float h;
    h = __uint_as_float(f2tf(v.x)); hi[o + 0] = h; lo[o + 0] = v.x - h;
    h = __uint_as_float(f2tf(v.y)); hi[o + 1] = h; lo[o + 1] = v.y - h;
    h = __uint_as_float(f2tf(v.z)); hi[o + 2] = h; lo[o + 2] = v.z - h;
    h = __uint_as_float(f2tf(v.w)); hi[o + 3] = h; lo[o + 3] = v.w - h;
}

// ----- packed f32x2 helpers (gram kernel) -----
__device__ __forceinline__ ull pack2s(float x) {
    ull r; asm("mov.b64 %0, {%1, %1};" : "=l"(r) : "f"(x)); return r;
}
__device__ __forceinline__ void ffma2(ull& d, ull a, ull b) {
    asm("fma.rn.f32x2 %0, %1, %2, %0;" : "+l"(d) : "l"(a), "l"(b));
}
__device__ __forceinline__ void unpack2(float& lo, float& hi, ull v) {
    asm("mov.b64 {%0, %1}, %2;" : "=f"(lo), "=f"(hi) : "l"(v));
}
__device__ __forceinline__ void fma8x8p(ull (&acc)[8][4],
                                        const float4 a0, const float4 a1,
                                        const ulonglong2 b01, const ulonglong2 b23) {
    float av[8] = {a0.x, a0.y, a0.z, a0.w, a1.x, a1.y, a1.z, a1.w};
    ull bp[4] = {b01.x, b01.y, b23.x, b23.y};
#pragma unroll
    for (int i = 0; i < 8; ++i) {
        ull ap = pack2s(av[i]);
        ffma2(acc[i][0], ap, bp[0]);
        ffma2(acc[i][1], ap, bp[1]);
        ffma2(acc[i][2], ap, bp[2]);
        ffma2(acc[i][3], ap, bp[3]);
    }
}

// ============================================================
// Pad ctx into [b][d][384]
// ============================================================
__global__ void pad_kernel(const float* __restrict__ lf) {
    size_t i = (size_t)blockIdx.x * blockDim.x + threadIdx.x;
    if (i < (size_t)NB * NC * SPAD) {
        int x = (int)(i % SPAD);
        size_t r = i / SPAD;
        g_ctxp[i] = (x < NS) ? lf[r * NS + x] : 0.f;
    }
}

// ============================================================
// Gram (FFMA f32x2 version — small: 3.6 G MACs)
// ============================================================
__global__ __launch_bounds__(256) void gram_kernel() {
    const int byA[6] = {0, 0, 0, 1, 1, 2};
    const int bxA[6] = {0, 1, 2, 1, 2, 2};
    int p = blockIdx.x, b = blockIdx.y;
    int i0 = byA[p] * 128, j0 = bxA[p] * 128;
    __shared__ float At[32 * 128];
    __shared__ float Bt[32 * 128];
    const float* cp = g_ctxp + (size_t)b * NC * SPAD;
    int tid = threadIdx.x;
    int ti = tid & 15, si = tid >> 4;
    int il = si * 8, jl = ti * 8;
    ull acc[8][4] = {};
    for (int kc = 0; kc < 24; ++kc) {
        int k0 = kc * 32;
        __syncthreads();
        for (int i4 = tid; i4 < 1024; i4 += 256) {
            int kk = i4 >> 5, x4 = i4 & 31;
            const float* base = cp + (size_t)(k0 + kk) * SPAD;
            ((float4*)At)[i4] = *(const float4*)(base + i0 + x4 * 4);
            ((float4*)Bt)[i4] = *(const float4*)(base + j0 + x4 * 4);
        }
        __syncthreads();
#pragma unroll 4
        for (int k = 0; k < 32; ++k) {
            float4 a0 = *(const float4*)&At[k * 128 + il];
            float4 a1 = *(const float4*)&At[k * 128 + il + 4];
            ulonglong2 b01 = *(const ulonglong2*)&Bt[k * 128 + jl];
            ulonglong2 b23 = *(const ulonglong2*)&Bt[k * 128 + jl + 4];
            fma8x8p(acc, a0, a1, b01, b23);
        }
    }
    float c[8][8];
#pragma unroll
    for (int ii = 0; ii < 8; ++ii)
#pragma unroll
        for (int j = 0; j < 4; ++j)
            unpack2(c[ii][2 * j], c[ii][2 * j + 1], acc[ii][j]);
    float* Gb = g_G + (size_t)b * SPAD * SPAD;
#pragma unroll
    for (int ii = 0; ii < 8; ++ii) {
        int row = i0 + il + ii;
        *(float4*)&Gb[(size_t)row * SPAD + j0 + jl] =
            make_float4(c[ii][0], c[ii][1], c[ii][2], c[ii][3]);
        *(float4*)&Gb[(size_t)row * SPAD + j0 + jl + 4] =
            make_float4(c[ii][4], c[ii][5], c[ii][6], c[ii][7]);
    }
    if (i0 != j0) {
#pragma unroll
        for (int jj = 0; jj < 8; ++jj) {
            int row = j0 + jl + jj;
#pragma unroll
            for (int ii = 0; ii < 8; ++ii)
                Gb[(size_t)row * SPAD + i0 + il + ii] = c[ii][jj];
        }
    }
}

// ============================================================
// Norms + global scores (unchanged)
// ============================================================
__global__ void norms_kernel(const float* __restrict__ words,
                             const float* __restrict__ gfeat,
                             const float* __restrict__ sfeat) {
    int c = blockIdx.x;
    int tid = threadIdx.x;
    float s = 0.f;
    for (int d = 0; d < NC; ++d) {
        float v = words[((size_t)c * NC + d) * NT + tid];
        s = fmaf(v, v, s);
    }
    g_w1n[c * NT + tid] = sqrtf(s);
    float a = 0.f, bb = 0.f;
    for (int d = tid; d < NC; d += 64) {
        float v = gfeat[(size_t)c * NC + d];
        float w = sfeat[(size_t)c * NC + d];
        a = fmaf(v, v, a);
        bb = fmaf(w, w, bb);
    }
#pragma unroll
    for (int o = 16; o; o >>= 1) {
        a  += __shfl_xor_sync(0xffffffffu, a, o);
        bb += __shfl_xor_sync(0xffffffffu, bb, o);
    }
    __shared__ float r[4];
    int warp = tid >> 5, lane = tid & 31;
    if (lane == 0) { r[warp] = a; r[2 + warp] = bb; }
    __syncthreads();
    if (tid == 0) {
        g_gn[c] = sqrtf(r[0] + r[1]);
        g_sn[c] = sqrtf(r[2] + r[3]);
    }
}

__global__ void gscore_kernel(const float* __restrict__ gfeat,
                              const float* __restrict__ sfeat) {
    int i = blockIdx.x;
    int tid = threadIdx.x;
    int warp = tid >> 5, lane = tid & 31;
    for (int j = warp; j < NB; j += 8) {
        float acc = 0.f;
        for (int d = lane; d < NC; d += 32)
            acc = fmaf(gfeat[(size_t)i * NC + d], sfeat[(size_t)j * NC + d], acc);
#pragma unroll
        for (int o = 16; o; o >>= 1) acc += __shfl_xor_sync(0xffffffffu, acc, o);
        if (lane == 0) {
            float denom = fmaxf(g_gn[i] * g_sn[j], EPSV);
            g_sc0[i * NB + j] = TEMP3 * acc / denom;
        }
    }
}

// ============================================================
// Kernel A: tensor scores + fused softmax -> a2u, colsum, w12
// grid NPAIR, 256 threads (8 warps x 16 rows x 64 cols)
// smem floats: cth 4224 | ctl 4224 | wth 2176 | wtl 2176 | redc 512 | redw 512
// ============================================================
#define A_SMEM_FLOATS 13824
#define A_SMEM_BYTES  (A_SMEM_FLOATS * 4)

__global__ __launch_bounds__(256, 2) void scoreA_kernel(
    const float* __restrict__ words, const int* __restrict__ caps) {
    extern __shared__ float sm[];
    float* cth = sm;
    float* ctl = sm + 4224;
    float* wth = sm + 8448;
    float* wtl = sm + 10624;
    float* redc = sm + 12800;
    float* redw = sm + 13312;

    int tid = threadIdx.x, wid = tid >> 5, lane = tid & 31;
    int g = lane >> 2, tg = lane & 3;
    int p = blockIdx.x, b = p % NB, c = p / NB;
    const float* cpx = g_ctxp + (size_t)b * NC * SPAD;
    const float* wrd = words + (size_t)c * NC * NT;
    int cap = caps[c];

    float colacc[16] = {}, w12acc[16] = {};

    for (int st = 0; st < 3; ++st) {
        int s_base = st * 128;
        float acc[8][4] = {};
        for (int kc = 0; kc < 24; ++kc) {
            int k0 = kc * 32;
            __syncthreads();
            for (int i4 = tid; i4 < 1024; i4 += 256) {
                int kk = i4 >> 5, x4 = i4 & 31;
                float4 v = *(const float4*)(cpx + (size_t)(k0 + kk) * SPAD + s_base + x4 * 4);
                split4(cth, ctl, kk * 132 + x4 * 4, v);
            }
            for (int i4 = tid; i4 < 512; i4 += 256) {
                int kk = i4 >> 4, x4 = i4 & 15;
                float4 v = *(const float4*)(wrd + (size_t)(k0 + kk) * NT + x4 * 4);
                split4(wth, wtl, kk * 68 + x4 * 4, v);
            }
            __syncthreads();
            int arow = wid * 16 + g;
#pragma unroll
            for (int k8 = 0; k8 < 4; ++k8) {
                int kb = k8 * 8;
                int ao0 = (kb + tg) * 132 + arow;
                int ao1 = (kb + tg + 4) * 132 + arow;
                uint32_t ah0 = __float_as_uint(cth[ao0]);
                uint32_t ah1 = __float_as_uint(cth[ao0 + 8]);
                uint32_t ah2 = __float_as_uint(cth[ao1]);
                uint32_t ah3 = __float_as_uint(cth[ao1 + 8]);
                uint32_t al0 = __float_as_uint(ctl[ao0]);
                uint32_t al1 = __float_as_uint(ctl[ao0 + 8]);
                uint32_t al2 = __float_as_uint(ctl[ao1]);
                uint32_t al3 = __float_as_uint(ctl[ao1 + 8]);
#pragma unroll
                for (int nt = 0; nt < 8; ++nt) {
                    int bo0 = (kb + tg) * 68 + nt * 8 + g;
                    int bo1 = (kb + tg + 4) * 68 + nt * 8 + g;
                    uint32_t bh0 = __float_as_uint(wth[bo0]);
                    uint32_t bh1 = __float_as_uint(wth[bo1]);
                    uint32_t bl0 = __float_as_uint(wtl[bo0]);
                    uint32_t bl1 = __float_as_uint(wtl[bo1]);
                    mma8(acc[nt], ah0, ah1, ah2, ah3, bh0, bh1);
                    mma8(acc[nt], ah0, ah1, ah2, ah3, bl0, bl1);
                    mma8(acc[nt], al0, al1, al2, al3, bh0, bh1);
                }
            }
        }
        // ---- fused masked softmax over t (row in one lane-quad) ----
        int s0 = s_base + wid * 16 + g;
        int s1 = s0 + 8;
        float mx0 = -1e30f, mx1 = -1e30f;
#pragma unroll
        for (int nt = 0; nt < 8; ++nt) {
            int col = nt * 8 + 2 * tg;
            if (col < cap)     { mx0 = fmaxf(mx0, acc[nt][0]); mx1 = fmaxf(mx1, acc[nt][2]); }
            if (col + 1 < cap) { mx0 = fmaxf(mx0, acc[nt][1]); mx1 = fmaxf(mx1, acc[nt][3]); }
        }
        mx0 = fmaxf(mx0, __shfl_xor_sync(0xffffffffu, mx0, 1));
        mx0 = fmaxf(mx0, __shfl_xor_sync(0xffffffffu, mx0, 2));
        mx1 = fmaxf(mx1, __shfl_xor_sync(0xffffffffu, mx1, 1));
        mx1 = fmaxf(mx1, __shfl_xor_sync(0xffffffffu, mx1, 2));
        float sm0 = 0.f, sm1 = 0.f;
#pragma unroll
        for (int nt = 0; nt < 8; ++nt) {
            int col = nt * 8 + 2 * tg;
            if (col < cap)     { sm0 += __expf(acc[nt][0] - mx0); sm1 += __expf(acc[nt][2] - mx1); }
            if (col + 1 < cap) { sm0 += __expf(acc[nt][1] - mx0); sm1 += __expf(acc[nt][3] - mx1); }
        }
        sm0 += __shfl_xor_sync(0xffffffffu, sm0, 1);
        sm0 += __shfl_xor_sync(0xffffffffu, sm0, 2);
        sm1 += __shfl_xor_sync(0xffffffffu, sm1, 1);
        sm1 += __shfl_xor_sync(0xffffffffu, sm1, 2);
        float inv0 = 1.f / sm0, inv1 = 1.f / sm1;
        bool v0ok = (s0 < NS), v1ok = (s1 < NS);
        float* au = g_a2u + (size_t)p * SPAD * NT;
#pragma unroll
        for (int nt = 0; nt < 8; ++nt) {
            int col = nt * 8 + 2 * tg;
            float e00 = (col < cap)     ? __expf(acc[nt][0] - mx0) : 0.f;
            float e01 = (col + 1 < cap) ? __expf(acc[nt][1] - mx0) : 0.f;
            float e10 = (col < cap)     ? __expf(acc[nt][2] - mx1) : 0.f;
            float e11 = (col + 1 < cap) ? __expf(acc[nt][3] - mx1) : 0.f;
            float u00 = __expf(TEMP1 * (e00 * inv0));
            float u01 = __expf(TEMP1 * (e01 * inv0));
            float u10 = __expf(TEMP1 * (e10 * inv1));
            float u11 = __expf(TEMP1 * (e11 * inv1));
            float a00 = v0ok ? u00 : 0.f, a01 = v0ok ? u01 : 0.f;
            float a10 = v1ok ? u10 : 0.f, a11 = v1ok ? u11 : 0.f;
            colacc[nt * 2 + 0] += a00 + a10;
            colacc[nt * 2 + 1] += a01 + a11;
            w12acc[nt * 2 + 0] += (v0ok ? u00 * acc[nt][0] : 0.f) + (v1ok ? u10 * acc[nt][2] : 0.f);
            w12acc[nt * 2 + 1] += (v0ok ? u01 * acc[nt][1] : 0.f) + (v1ok ? u11 * acc[nt][3] : 0.f);
            *(float2*)&au[(size_t)s0 * NT + col] = make_float2(a00, a01);
            *(float2*)&au[(size_t)s1 * NT + col] = make_float2(a10, a11);
        }
    }
    // reduce across the 8 g-lanes (stride-4 xor)
#pragma unroll
    for (int i = 0; i < 16; ++i) {
        float v = colacc[i], w = w12acc[i];
        v += __shfl_xor_sync(0xffffffffu, v, 4);
        v += __shfl_xor_sync(0xffffffffu, v, 8);
        v += __shfl_xor_sync(0xffffffffu, v, 16);
        w += __shfl_xor_sync(0xffffffffu, w, 4);
        w += __shfl_xor_sync(0xffffffffu, w, 8);
        w += __shfl_xor_sync(0xffffffffu, w, 16);
        colacc[i] = v; w12acc[i] = w;
    }
    if (g == 0) {
#pragma unroll
        for (int i = 0; i < 16; ++i) {
            int col = (i >> 1) * 8 + 2 * tg + (i & 1);
            redc[wid * 64 + col] = colacc[i];
            redw[wid * 64 + col] = w12acc[i];
        }
    }
    __syncthreads();
    if (tid < 64) {
        float cs = 0.f, ws = 0.f;
#pragma unroll
        for (int w = 0; w < 8; ++w) { cs += redc[w * 64 + tid]; ws += redw[w * 64 + tid]; }
        g_cols[p * 64 + tid] = cs;
        g_w12[p * 64 + tid] = ws;
    }
}

// ============================================================
// Kernel B: tensor Y = G_b @ a2u, contract -> w2raw
// grid NPAIR, 256 threads
// smem floats: cth 4224 | ctl 4224 | ath 2176 | atl 2176 | w2red 512
// ============================================================
#define B_SMEM_FLOATS 13312
#define B_SMEM_BYTES  (B_SMEM_FLOATS * 4)

__global__ __launch_bounds__(256, 2) void w2B_kernel() {
    extern __shared__ float sm[];
    float* cth = sm;
    float* ctl = sm + 4224;
    float* ath = sm + 8448;
    float* atl = sm + 10624;
    float* w2red = sm + 12800;

    int tid = threadIdx.x, wid = tid >> 5, lane = tid & 31;
    int g = lane >> 2, tg = lane & 3;
    int p = blockIdx.x, b = p % NB;
    const float* Gb = g_G + (size_t)b * SPAD * SPAD;
    const float* au = g_a2u + (size_t)p * SPAD * NT;

    float w2acc[16] = {};

    for (int st = 0; st < 3; ++st) {
        int s_base = st * 128;
        float acc[8][4] = {};
        for (int kc = 0; kc < 12; ++kc) {
            int k0 = kc * 32;
            __syncthreads();
            for (int i4 = tid; i4 < 1024; i4 += 256) {
                int kk = i4 >> 5, x4 = i4 & 31;
                float4 v = *(const float4*)(Gb + (size_t)(k0 + kk) * SPAD + s_base + x4 * 4);
                split4(cth, ctl, kk * 132 + x4 * 4, v);
            }
            for (int i4 = tid; i4 < 512; i4 += 256) {
                int kk = i4 >> 4, x4 = i4 & 15;
                float4 v = *(const float4*)(au + (size_t)(k0 + kk) * NT + x4 * 4);
                split4(ath, atl, kk * 68 + x4 * 4, v);
            }
            __syncthreads();
            int arow = wid * 16 + g;
#pragma unroll
            for (int k8 = 0; k8 < 4; ++k8) {
                int kb = k8 * 8;
                int ao0 = (kb + tg) * 132 + arow;
                int ao1 = (kb + tg + 4) * 132 + arow;
                uint32_t ah0 = __float_as_uint(cth[ao0]);
                uint32_t ah1 = __float_as_uint(cth[ao0 + 8]);
                uint32_t ah2 = __float_as_uint(cth[ao1]);
                uint32_t ah3 = __float_as_uint(cth[ao1 + 8]);
                uint32_t al0 = __float_as_uint(ctl[ao0]);
                uint32_t al1 = __float_as_uint(ctl[ao0 + 8]);
                uint32_t al2 = __float_as_uint(ctl[ao1]);
                uint32_t al3 = __float_as_uint(ctl[ao1 + 8]);
#pragma unroll
                for (int nt = 0; nt < 8; ++nt) {
                    int bo0 = (kb + tg) * 68 + nt * 8 + g;
                    int bo1 = (kb + tg + 4) * 68 + nt * 8 + g;
                    uint32_t bh0 = __float_as_uint(ath[bo0]);
                    uint32_t bh1 = __float_as_uint(ath[bo1]);
                    uint32_t bl0 = __float_as_uint(atl[bo0]);
                    uint32_t bl1 = __float_as_uint(atl[bo1]);
                    mma8(acc[nt], ah0, ah1, ah2, ah3, bh0, bh1);
                    mma8(acc[nt], ah0, ah1, ah2, ah3, bl0, bl1);
                    mma8(acc[nt], al0, al1, al2, al3, bh0, bh1);
                }
            }
        }
        // contraction: w2raw[t] += a2u[s,t] * Y[s,t]
        int s0 = s_base + wid * 16 + g;
        int s1 = s0 + 8;
#pragma unroll
        for (int nt = 0; nt < 8; ++nt) {
            int col = nt * 8 + 2 * tg;
            float2 a0v = *(const float2*)&au[(size_t)s0 * NT + col];
            float2 a1v = *(const float2*)&au[(size_t)s1 * NT + col];
            w2acc[nt * 2 + 0] += a0v.x * acc[nt][0] + a1v.x * acc[nt][2];
            w2acc[nt * 2 + 1] += a0v.y * acc[nt][1] + a1v.y * acc[nt][3];
        }
    }
#pragma unroll
    for (int i = 0; i < 16; ++i) {
        float v = w2acc[i];
        v += __shfl_xor_sync(0xffffffffu, v, 4);
        v += __shfl_xor_sync(0xffffffffu, v, 8);
        v += __shfl_xor_sync(0xffffffffu, v, 16);
        w2acc[i] = v;
    }
    if (g == 0) {
#pragma unroll
        for (int i = 0; i < 16; ++i) {
            int col = (i >> 1) * 8 + 2 * tg + (i & 1);
            w2red[wid * 64 + col] = w2acc[i];
        }
    }
    __syncthreads();
    if (tid < 64) {
        float s = 0.f;
#pragma unroll
        for (int w = 0; w < 8; ++w) s += w2red[w * 64 + tid];
        g_w2[p * 64 + tid] = s;
    }
}

// ============================================================
// Kernel C: similarity row per pair
// ============================================================
__global__ void csim_kernel(const int* __restrict__ caps) {
    int p = blockIdx.x, b = p % NB, c = p / NB;
    int t = threadIdx.x;
    float cs = g_cols[p * 64 + t];
    float ci = 1.f / cs;
    float w12 = g_w12[p * 64 + t] * ci;
    float w2 = ci * sqrtf(g_w2[p * 64 + t]);
    float w1 = g_w1n[c * 64 + t];
    float sim = w12 / fmaxf(w1 * w2, EPSV);
    float row = (t < caps[c]) ? __expf(TEMP2 * sim) : 0.f;
#pragma unroll
    for (int o = 16; o; o >>= 1) row += __shfl_xor_sync(0xffffffffu, row, o);
    __shared__ float sred[2];
    if ((t & 31) == 0) sred[t >> 5] = row;
    __syncthreads();
    if (t == 0) g_sims[b * NB + c] = TEMP3 * logf(sred[0] + sred[1]);
}

// ============================================================
// att maps for diagonal pairs
// ============================================================
__global__ void att_kernel(float* __restrict__ ao) {
    int b = blockIdx.x;
    int p = b * NB + b;
    int tid = threadIdx.x;
    __shared__ float ci[64];
    if (tid < 64) ci[tid] = 1.f / g_cols[p * 64 + tid];
    __syncthreads();
    const float* au = g_a2u + (size_t)p * SPAD * NT;
    for (int i = tid; i < NS * NT; i += 256) {
        int s = i >> 6, t = i & 63;
        ao[((size_t)b * NT + t) * NS + s] = au[(size_t)s * NT + t] * ci[t];
    }
}

// ============================================================
// Final loss
// ============================================================
__global__ void loss_kernel(float* __restrict__ out) {
    __shared__ float part[4][NB];
    int i = threadIdx.x;
    if (i < NB) {
        const float* Ms = g_sims;
        const float* Mg = g_sc0;
        float m, sum;
        m = -INFINITY;
        for (int j = 0; j < NB; ++j) m = fmaxf(m, Ms[i * NB + j]);
        sum = 0.f;
        for (int j = 0; j < NB; ++j) sum += expf(Ms[i * NB + j] - m);
        part[0][i] = m + logf(sum) - Ms[i * NB + i];
        m = -INFINITY;
        for (int j = 0; j < NB; ++j) m = fmaxf(m, Ms[j * NB + i]);
        sum = 0.f;
        for (int j = 0; j < NB; ++j) sum += expf(Ms[j * NB + i] - m);
        part[1][i] = m + logf(sum) - Ms[i * NB + i];
        m = -INFINITY;
        for (int j = 0; j < NB; ++j) m = fmaxf(m, Mg[i * NB + j]);
        sum = 0.f;
        for (int j = 0; j < NB; ++j) sum += expf(Mg[i * NB + j] - m);
        part[2][i] = m + logf(sum) - Mg[i * NB + i];
        m = -INFINITY;
        for (int j = 0; j < NB; ++j) m = fmaxf(m, Mg[j * NB + i]);
        sum = 0.f;
        for (int j = 0; j < NB; ++j) sum += expf(Mg[j * NB + i] - m);
        part[3][i] = m + logf(sum) - Mg[i * NB + i];
    }
    __syncthreads();
    if (i == 0) {
        float l = 0.f;
        for (int k = 0; k < 4; ++k) {
            float s = 0.f;
            for (int j = 0; j < NB; ++j) s += part[k][j];
            l += s * (1.f / (float)NB);
        }
        out[0] = l;
    }
}

// ============================================================
extern "C" void kernel_launch(void* const* d_in, const int* in_sizes, int n_in,
                              void* d_out, int out_size) {
    const float* gfeat  = (const float*)d_in[0];
    const float* localf = (const float*)d_in[1];
    const float* words  = (const float*)d_in[2];
    const float* sfeat  = (const float*)d_in[3];
    const int*   caps   = (const int*)d_in[4];
    float* out = (float*)d_out;

    cudaFuncSetAttribute(scoreA_kernel, cudaFuncAttributeMaxDynamicSharedMemorySize, A_SMEM_BYTES);
    cudaFuncSetAttribute(w2B_kernel, cudaFuncAttributeMaxDynamicSharedMemorySize, B_SMEM_BYTES);

    size_t tot = (size_t)NB * NC * SPAD;
    pad_kernel<<<(unsigned)((tot + 255) / 256), 256>>>(localf);
    gram_kernel<<<dim3(6, NB), 256>>>();
    norms_kernel<<<NB, 64>>>(words, gfeat, sfeat);
    gscore_kernel<<<NB, 256>>>(gfeat, sfeat);

    scoreA_kernel<<<NPAIR, 256, A_SMEM_BYTES>>>(words, caps);
    w2B_kernel<<<NPAIR, 256, B_SMEM_BYTES>>>();
    csim_kernel<<<NPAIR, 64>>>(caps);

    int wa = (out_size >= 1 + NB * NT * NS) ? 1 : 0;
    if (wa) att_kernel<<<NB, 256>>>(out + 1);
    loss_kernel<<<1, 64>>>(out);
}

// round 9
// speedup vs baseline: 1.2194x; 1.2194x over previous
#include <cuda_runtime.h>
#include <math.h>
#include <stdint.h>

#define NB 48
#define NC 768
#define NS 361
#define NT 64
#define SPAD 384
#define NPAIR (NB * NB)

#define TEMP1 4.0f
#define TEMP2 5.0f
#define TEMP3 10.0f
#define EPSV  1e-8f

typedef unsigned long long ull;

// ================= device scratch =================
__device__ float g_ctxp[(size_t)NB * NC * SPAD];   // padded ctx [b][d][384] (gram input)
__device__ float g_G[(size_t)NB * SPAD * SPAD];    // fp32 Gram [b][s][s']
__device__ float g_ctxH[(size_t)NB * NC * SPAD];   // tf32-hi ctx [b][d][s]
__device__ float g_ctxL[(size_t)NB * NC * SPAD];   // residual lo
__device__ float g_wH[(size_t)NB * NC * NT];       // tf32-hi words [c][d][t]
__device__ float g_wL[(size_t)NB * NC * NT];
__device__ float g_GH[(size_t)NB * SPAD * SPAD];   // tf32-hi G
__device__ float g_GL[(size_t)NB * SPAD * SPAD];
__device__ float g_a2uH[(size_t)NPAIR * SPAD * NT]; // a2u hi [p][s][t]
__device__ float g_a2uL[(size_t)NPAIR * SPAD * NT]; // a2u lo
__device__ float g_cols[NPAIR * NT];
__device__ float g_w12[NPAIR * NT];
__device__ float g_w2[NPAIR * NT];
__device__ float g_w1n[NB * NT];
__device__ float g_gn[NB];
__device__ float g_sn[NB];
__device__ float g_sc0[NB * NB];
__device__ float g_sims[NB * NB];

// ================= helpers =================
__device__ __forceinline__ float tf32f(float v) {
    uint32_t r;
    asm("cvt.rna.tf32.f32 %0, %1;" : "=r"(r) : "f"(v));
    return __uint_as_float(r);
}
__device__ __forceinline__ void mma8(float* c, uint32_t a0, uint32_t a1,
                                     uint32_t a2, uint32_t a3,
                                     uint32_t b0, uint32_t b1) {
    asm volatile(
        "mma.sync.aligned.m16n8k8.row.col.f32.tf32.tf32.f32 "
        "{%0,%1,%2,%3}, {%4,%5,%6,%7}, {%8,%9}, {%0,%1,%2,%3};"
        : "+f"(c[0]), "+f"(c[1]), "+f"(c[2]), "+f"(c[3])
        : "r"(a0), "r"(a1), "r"(a2), "r"(a3), "r"(b0), "r"(b1));
}
__device__ __forceinline__ uint32_t smem_u32(const void* p) {
    uint32_t a;
    asm("{ .reg .u64 t; cvta.to.shared.u64 t, %1; cvt.u32.u64 %0, t; }"
        : "=r"(a) : "l"(p));
    return a;
}
__device__ __forceinline__ void cpa16(uint32_t dst, const void* src) {
    asm volatile("cp.async.cg.shared.global [%0], [%1], 16;"
                 :: "r"(dst), "l"(src));
}
#define CPA_COMMIT() asm volatile("cp.async.commit_group;")
#define CPA_WAIT0()  asm volatile("cp.async.wait_group 0;")

// ================= prep kernels =================
__global__ void pad_kernel(const float* __restrict__ lf) {
    size_t i = (size_t)blockIdx.x * blockDim.x + threadIdx.x;
    if (i < (size_t)NB * NC * SPAD) {
        int x = (int)(i % SPAD);
        size_t r = i / SPAD;
        g_ctxp[i] = (x < NS) ? lf[r * NS + x] : 0.f;
    }
}
__global__ void prep_ctx(const float* __restrict__ lf) {
    size_t i = (size_t)blockIdx.x * blockDim.x + threadIdx.x;
    if (i >= (size_t)NB * NC * SPAD) return;
    int x = (int)(i % SPAD);
    size_t r = i / SPAD;
    float v = (x < NS) ? lf[r * NS + x] : 0.f;
    float h = tf32f(v);
    g_ctxH[i] = h;
    g_ctxL[i] = v - h;
}
__global__ void prep_w(const float* __restrict__ w) {
    size_t i = (size_t)blockIdx.x * blockDim.x + threadIdx.x;
    if (i >= (size_t)NB * NC * NT) return;
    float v = w[i];
    float h = tf32f(v);
    g_wH[i] = h;
    g_wL[i] = v - h;
}
__global__ void prep_G() {
    size_t i = (size_t)blockIdx.x * blockDim.x + threadIdx.x;
    if (i >= (size_t)NB * SPAD * SPAD) return;
    float v = g_G[i];
    float h = tf32f(v);
    g_GH[i] = h;
    g_GL[i] = v - h;
}

// ================= gram (FFMA f32x2) =================
__device__ __forceinline__ ull pack2s(float x) {
    ull r; asm("mov.b64 %0, {%1, %1};" : "=l"(r) : "f"(x)); return r;
}
__device__ __forceinline__ void ffma2(ull& d, ull a, ull b) {
    asm("fma.rn.f32x2 %0, %1, %2, %0;" : "+l"(d) : "l"(a), "l"(b));
}
__device__ __forceinline__ void unpack2(float& lo, float& hi, ull v) {
    asm("mov.b64 {%0, %1}, %2;" : "=f"(lo), "=f"(hi) : "l"(v));
}
__device__ __forceinline__ void fma8x8p(ull (&acc)[8][4],
                                        const float4 a0, const float4 a1,
                                        const ulonglong2 b01, const ulonglong2 b23) {
    float av[8] = {a0.x, a0.y, a0.z, a0.w, a1.x, a1.y, a1.z, a1.w};
    ull bp[4] = {b01.x, b01.y, b23.x, b23.y};
#pragma unroll
    for (int i = 0; i < 8; ++i) {
        ull ap = pack2s(av[i]);
        ffma2(acc[i][0], ap, bp[0]);
        ffma2(acc[i][1], ap, bp[1]);
        ffma2(acc[i][2], ap, bp[2]);
        ffma2(acc[i][3], ap, bp[3]);
    }
}

__global__ __launch_bounds__(256) void gram_kernel() {
    const int byA[6] = {0, 0, 0, 1, 1, 2};
    const int bxA[6] = {0, 1, 2, 1, 2, 2};
    int p = blockIdx.x, b = blockIdx.y;
    int i0 = byA[p] * 128, j0 = bxA[p] * 128;
    __shared__ float At[32 * 128];
    __shared__ float Bt[32 * 128];
    const float* cp = g_ctxp + (size_t)b * NC * SPAD;
    int tid = threadIdx.x;
    int ti = tid & 15, si = tid >> 4;
    int il = si * 8, jl = ti * 8;
    ull acc[8][4] = {};
    for (int kc = 0; kc < 24; ++kc) {
        int k0 = kc * 32;
        __syncthreads();
        for (int i4 = tid; i4 < 1024; i4 += 256) {
            int kk = i4 >> 5, x4 = i4 & 31;
            const float* base = cp + (size_t)(k0 + kk) * SPAD;
            ((float4*)At)[i4] = *(const float4*)(base + i0 + x4 * 4);
            ((float4*)Bt)[i4] = *(const float4*)(base + j0 + x4 * 4);
        }
        __syncthreads();
#pragma unroll 4
        for (int k = 0; k < 32; ++k) {
            float4 a0 = *(const float4*)&At[k * 128 + il];
            float4 a1 = *(const float4*)&At[k * 128 + il + 4];
            ulonglong2 b01 = *(const ulonglong2*)&Bt[k * 128 + jl];
            ulonglong2 b23 = *(const ulonglong2*)&Bt[k * 128 + jl + 4];
            fma8x8p(acc, a0, a1, b01, b23);
        }
    }
    float c[8][8];
#pragma unroll
    for (int ii = 0; ii < 8; ++ii)
#pragma unroll
        for (int j = 0; j < 4; ++j)
            unpack2(c[ii][2 * j], c[ii][2 * j + 1], acc[ii][j]);
    float* Gb = g_G + (size_t)b * SPAD * SPAD;
#pragma unroll
    for (int ii = 0; ii < 8; ++ii) {
        int row = i0 + il + ii;
        *(float4*)&Gb[(size_t)row * SPAD + j0 + jl] =
            make_float4(c[ii][0], c[ii][1], c[ii][2], c[ii][3]);
        *(float4*)&Gb[(size_t)row * SPAD + j0 + jl + 4] =
            make_float4(c[ii][4], c[ii][5], c[ii][6], c[ii][7]);
    }
    if (i0 != j0) {
#pragma unroll
        for (int jj = 0; jj < 8; ++jj) {
            int row = j0 + jl + jj;
#pragma unroll
            for (int ii = 0; ii < 8; ++ii)
                Gb[(size_t)row * SPAD + i0 + il + ii] = c[ii][jj];
        }
    }
}

// ================= norms / gscore =================
__global__ void norms_kernel(const float* __restrict__ words,
                             const float* __restrict__ gfeat,
                             const float* __restrict__ sfeat) {
    int c = blockIdx.x;
    int tid = threadIdx.x;
    float s = 0.f;
    for (int d = 0; d < NC; ++d) {
        float v = words[((size_t)c * NC + d) * NT + tid];
        s = fmaf(v, v, s);
    }
    g_w1n[c * NT + tid] = sqrtf(s);
    float a = 0.f, bb = 0.f;
    for (int d = tid; d < NC; d += 64) {
        float v = gfeat[(size_t)c * NC + d];
        float w = sfeat[(size_t)c * NC + d];
        a = fmaf(v, v, a);
        bb = fmaf(w, w, bb);
    }
#pragma unroll
    for (int o = 16; o; o >>= 1) {
        a  += __shfl_xor_sync(0xffffffffu, a, o);
        bb += __shfl_xor_sync(0xffffffffu, bb, o);
    }
    __shared__ float r[4];
    int warp = tid >> 5, lane = tid & 31;
    if (lane == 0) { r[warp] = a; r[2 + warp] = bb; }
    __syncthreads();
    if (tid == 0) {
        g_gn[c] = sqrtf(r[0] + r[1]);
        g_sn[c] = sqrtf(r[2] + r[3]);
    }
}

__global__ void gscore_kernel(const float* __restrict__ gfeat,
                              const float* __restrict__ sfeat) {
    int i = blockIdx.x;
    int tid = threadIdx.x;
    int warp = tid >> 5, lane = tid & 31;
    for (int j = warp; j < NB; j += 8) {
        float acc = 0.f;
        for (int d = lane; d < NC; d += 32)
            acc = fmaf(gfeat[(size_t)i * NC + d], sfeat[(size_t)j * NC + d], acc);
#pragma unroll
        for (int o = 16; o; o >>= 1) acc += __shfl_xor_sync(0xffffffffu, acc, o);
        if (lane == 0) {
            float denom = fmaxf(g_gn[i] * g_sn[j], EPSV);
            g_sc0[i * NB + j] = TEMP3 * acc / denom;
        }
    }
}

// ================= Kernel A: tf32 mma scores + fused softmax =================
#define A_CTH 0
#define A_CTL 16896
#define A_WTH 33792
#define A_WTL 42496
#define A_REDC 51200
#define A_REDW 53248
#define A_SMEM 55296

__global__ __launch_bounds__(256, 2) void scoreA_kernel(const int* __restrict__ caps) {
    extern __shared__ char smc[];
    uint32_t smb = smem_u32(smc);
    float* cth = (float*)(smc + A_CTH);
    float* ctl = (float*)(smc + A_CTL);
    float* wth = (float*)(smc + A_WTH);
    float* wtl = (float*)(smc + A_WTL);
    float* redc = (float*)(smc + A_REDC);
    float* redw = (float*)(smc + A_REDW);

    int tid = threadIdx.x, wid = tid >> 5, lane = tid & 31;
    int g = lane >> 2, tg = lane & 3;
    int p = blockIdx.x, b = p % NB, c = p / NB;
    const float* cH = g_ctxH + (size_t)b * NC * SPAD;
    const float* cL = g_ctxL + (size_t)b * NC * SPAD;
    const float* wH = g_wH + (size_t)c * NC * NT;
    const float* wL = g_wL + (size_t)c * NC * NT;
    int cap = caps[c];
    int capN = (cap + 7) >> 3;
    int bsegs = 2 * capN;          // 16B segments per B-tile row

    float colacc[16] = {}, w12acc[16] = {};
    float* auH = g_a2uH + (size_t)p * SPAD * NT;
    float* auL = g_a2uL + (size_t)p * SPAD * NT;

    for (int st = 0; st < 3; ++st) {
        int s_base = st * 128;
        float acc[8][4] = {};
        for (int kc = 0; kc < 24; ++kc) {
            int k0 = kc * 32;
            __syncthreads();
            // A tiles (hi+lo): 2048 16B segments
            for (int i = tid; i < 2048; i += 256) {
                int h = i >> 10;
                int j = i & 1023;
                int kk = j >> 5, x4 = j & 31;
                const float* src = (h ? cL : cH) + (size_t)(k0 + kk) * SPAD + s_base + x4 * 4;
                cpa16(smb + (h ? A_CTL : A_CTH) + (uint32_t)(kk * 132 + x4 * 4) * 4, src);
            }
            // B tiles (hi+lo): 32 rows x bsegs, only needed word columns
            int btot = 64 * bsegs;
            for (int i = tid; i < btot; i += 256) {
                int h = (i >= 32 * bsegs);
                int j = h ? i - 32 * bsegs : i;
                int kk = j / bsegs, x4 = j - kk * bsegs;
                const float* src = (h ? wL : wH) + (size_t)(k0 + kk) * NT + x4 * 4;
                cpa16(smb + (h ? A_WTL : A_WTH) + (uint32_t)(kk * 68 + x4 * 4) * 4, src);
            }
            CPA_COMMIT();
            CPA_WAIT0();
            __syncthreads();
            int arow = wid * 16 + g;
#pragma unroll
            for (int k8 = 0; k8 < 4; ++k8) {
                int kb = k8 * 8;
                int ao0 = (kb + tg) * 132 + arow;
                int ao1 = (kb + tg + 4) * 132 + arow;
                uint32_t ah0 = __float_as_uint(cth[ao0]);
                uint32_t ah1 = __float_as_uint(cth[ao0 + 8]);
                uint32_t ah2 = __float_as_uint(cth[ao1]);
                uint32_t ah3 = __float_as_uint(cth[ao1 + 8]);
                uint32_t al0 = __float_as_uint(ctl[ao0]);
                uint32_t al1 = __float_as_uint(ctl[ao0 + 8]);
                uint32_t al2 = __float_as_uint(ctl[ao1]);
                uint32_t al3 = __float_as_uint(ctl[ao1 + 8]);
#pragma unroll
                for (int nt = 0; nt < 8; ++nt) {
                    if (nt < capN) {
                        int bo0 = (kb + tg) * 68 + nt * 8 + g;
                        int bo1 = (kb + tg + 4) * 68 + nt * 8 + g;
                        uint32_t bh0 = __float_as_uint(wth[bo0]);
                        uint32_t bh1 = __float_as_uint(wth[bo1]);
                        uint32_t bl0 = __float_as_uint(wtl[bo0]);
                        uint32_t bl1 = __float_as_uint(wtl[bo1]);
                        mma8(acc[nt], ah0, ah1, ah2, ah3, bh0, bh1);
                        mma8(acc[nt], ah0, ah1, ah2, ah3, bl0, bl1);
                        mma8(acc[nt], al0, al1, al2, al3, bh0, bh1);
                    }
                }
            }
        }
        // ---- fused masked softmax over t (row lives in one lane-quad) ----
        int s0 = s_base + wid * 16 + g;
        int s1 = s0 + 8;
        float mx0 = -1e30f, mx1 = -1e30f;
#pragma unroll
        for (int nt = 0; nt < 8; ++nt) {
            int col = nt * 8 + 2 * tg;
            if (col < cap)     { mx0 = fmaxf(mx0, acc[nt][0]); mx1 = fmaxf(mx1, acc[nt][2]); }
            if (col + 1 < cap) { mx0 = fmaxf(mx0, acc[nt][1]); mx1 = fmaxf(mx1, acc[nt][3]); }
        }
        mx0 = fmaxf(mx0, __shfl_xor_sync(0xffffffffu, mx0, 1));
        mx0 = fmaxf(mx0, __shfl_xor_sync(0xffffffffu, mx0, 2));
        mx1 = fmaxf(mx1, __shfl_xor_sync(0xffffffffu, mx1, 1));
        mx1 = fmaxf(mx1, __shfl_xor_sync(0xffffffffu, mx1, 2));
        float sm0 = 0.f, sm1 = 0.f;
#pragma unroll
        for (int nt = 0; nt < 8; ++nt) {
            int col = nt * 8 + 2 * tg;
            if (col < cap)     { sm0 += __expf(acc[nt][0] - mx0); sm1 += __expf(acc[nt][2] - mx1); }
            if (col + 1 < cap) { sm0 += __expf(acc[nt][1] - mx0); sm1 += __expf(acc[nt][3] - mx1); }
        }
        sm0 += __shfl_xor_sync(0xffffffffu, sm0, 1);
        sm0 += __shfl_xor_sync(0xffffffffu, sm0, 2);
        sm1 += __shfl_xor_sync(0xffffffffu, sm1, 1);
        sm1 += __shfl_xor_sync(0xffffffffu, sm1, 2);
        float inv0 = 1.f / sm0, inv1 = 1.f / sm1;
        bool v0ok = (s0 < NS), v1ok = (s1 < NS);
#pragma unroll
        for (int nt = 0; nt < 8; ++nt) {
            int col = nt * 8 + 2 * tg;
            float e00 = (col < cap)     ? __expf(acc[nt][0] - mx0) : 0.f;
            float e01 = (col + 1 < cap) ? __expf(acc[nt][1] - mx0) : 0.f;
            float e10 = (col < cap)     ? __expf(acc[nt][2] - mx1) : 0.f;
            float e11 = (col + 1 < cap) ? __expf(acc[nt][3] - mx1) : 0.f;
            float u00 = __expf(TEMP1 * (e00 * inv0));
            float u01 = __expf(TEMP1 * (e01 * inv0));
            float u10 = __expf(TEMP1 * (e10 * inv1));
            float u11 = __expf(TEMP1 * (e11 * inv1));
            float a00 = v0ok ? u00 : 0.f, a01 = v0ok ? u01 : 0.f;
            float a10 = v1ok ? u10 : 0.f, a11 = v1ok ? u11 : 0.f;
            colacc[nt * 2 + 0] += a00 + a10;
            colacc[nt * 2 + 1] += a01 + a11;
            w12acc[nt * 2 + 0] += (v0ok ? u00 * acc[nt][0] : 0.f) + (v1ok ? u10 * acc[nt][2] : 0.f);
            w12acc[nt * 2 + 1] += (v0ok ? u01 * acc[nt][1] : 0.f) + (v1ok ? u11 * acc[nt][3] : 0.f);
            float h00 = tf32f(a00), h01 = tf32f(a01);
            float h10 = tf32f(a10), h11 = tf32f(a11);
            *(float2*)&auH[(size_t)s0 * NT + col] = make_float2(h00, h01);
            *(float2*)&auL[(size_t)s0 * NT + col] = make_float2(a00 - h00, a01 - h01);
            *(float2*)&auH[(size_t)s1 * NT + col] = make_float2(h10, h11);
            *(float2*)&auL[(size_t)s1 * NT + col] = make_float2(a10 - h10, a11 - h11);
        }
    }
#pragma unroll
    for (int i = 0; i < 16; ++i) {
        float v = colacc[i], w = w12acc[i];
        v += __shfl_xor_sync(0xffffffffu, v, 4);
        v += __shfl_xor_sync(0xffffffffu, v, 8);
        v += __shfl_xor_sync(0xffffffffu, v, 16);
        w += __shfl_xor_sync(0xffffffffu, w, 4);
        w += __shfl_xor_sync(0xffffffffu, w, 8);
        w += __shfl_xor_sync(0xffffffffu, w, 16);
        colacc[i] = v; w12acc[i] = w;
    }
    __syncthreads();
    if (g == 0) {
#pragma unroll
        for (int i = 0; i < 16; ++i) {
            int col = (i >> 1) * 8 + 2 * tg + (i & 1);
            redc[wid * 64 + col] = colacc[i];
            redw[wid * 64 + col] = w12acc[i];
        }
    }
    __syncthreads();
    if (tid < 64) {
        float cs = 0.f, ws = 0.f;
#pragma unroll
        for (int w = 0; w < 8; ++w) { cs += redc[w * 64 + tid]; ws += redw[w * 64 + tid]; }
        g_cols[p * 64 + tid] = cs;
        g_w12[p * 64 + tid] = ws;
    }
}

// ================= Kernel B: tf32 mma Gram quadratic form =================
#define B_CTH 0
#define B_CTL 16896
#define B_ATH 33792
#define B_ATL 42496
#define B_W2R 51200
#define B_SMEM 53248

__global__ __launch_bounds__(256, 2) void w2B_kernel(const int* __restrict__ caps) {
    extern __shared__ char smc[];
    uint32_t smb = smem_u32(smc);
    float* cth = (float*)(smc + B_CTH);
    float* ctl = (float*)(smc + B_CTL);
    float* ath = (float*)(smc + B_ATH);
    float* atl = (float*)(smc + B_ATL);
    float* w2red = (float*)(smc + B_W2R);

    int tid = threadIdx.x, wid = tid >> 5, lane = tid & 31;
    int g = lane >> 2, tg = lane & 3;
    int p = blockIdx.x, b = p % NB, c = p / NB;
    const float* GH = g_GH + (size_t)b * SPAD * SPAD;
    const float* GL = g_GL + (size_t)b * SPAD * SPAD;
    const float* aH = g_a2uH + (size_t)p * SPAD * NT;
    const float* aL = g_a2uL + (size_t)p * SPAD * NT;
    int cap = caps[c];
    int capN = (cap + 7) >> 3;
    int bsegs = 2 * capN;

    float w2acc[16] = {};

    for (int st = 0; st < 3; ++st) {
        int s_base = st * 128;
        float acc[8][4] = {};
        for (int kc = 0; kc < 12; ++kc) {
            int k0 = kc * 32;
            __syncthreads();
            for (int i = tid; i < 2048; i += 256) {
                int h = i >> 10;
                int j = i & 1023;
                int kk = j >> 5, x4 = j & 31;
                const float* src = (h ? GL : GH) + (size_t)(k0 + kk) * SPAD + s_base + x4 * 4;
                cpa16(smb + (h ? B_CTL : B_CTH) + (uint32_t)(kk * 132 + x4 * 4) * 4, src);
            }
            int btot = 64 * bsegs;
            for (int i = tid; i < btot; i += 256) {
                int h = (i >= 32 * bsegs);
                int j = h ? i - 32 * bsegs : i;
                int kk = j / bsegs, x4 = j - kk * bsegs;
                const float* src = (h ? aL : aH) + (size_t)(k0 + kk) * NT + x4 * 4;
                cpa16(smb + (h ? B_ATL : B_ATH) + (uint32_t)(kk * 68 + x4 * 4) * 4, src);
            }
            CPA_COMMIT();
            CPA_WAIT0();
            __syncthreads();
            int arow = wid * 16 + g;
#pragma unroll
            for (int k8 = 0; k8 < 4; ++k8) {
                int kb = k8 * 8;
                int ao0 = (kb + tg) * 132 + arow;
                int ao1 = (kb + tg + 4) * 132 + arow;
                uint32_t ah0 = __float_as_uint(cth[ao0]);
                uint32_t ah1 = __float_as_uint(cth[ao0 + 8]);
                uint32_t ah2 = __float_as_uint(cth[ao1]);
                uint32_t ah3 = __float_as_uint(cth[ao1 + 8]);
                uint32_t al0 = __float_as_uint(ctl[ao0]);
                uint32_t al1 = __float_as_uint(ctl[ao0 + 8]);
                uint32_t al2 = __float_as_uint(ctl[ao1]);
                uint32_t al3 = __float_as_uint(ctl[ao1 + 8]);
#pragma unroll
                for (int nt = 0; nt < 8; ++nt) {
                    if (nt < capN) {
                        int bo0 = (kb + tg) * 68 + nt * 8 + g;
                        int bo1 = (kb + tg + 4) * 68 + nt * 8 + g;
                        uint32_t bh0 = __float_as_uint(ath[bo0]);
                        uint32_t bh1 = __float_as_uint(ath[bo1]);
                        uint32_t bl0 = __float_as_uint(atl[bo0]);
                        uint32_t bl1 = __float_as_uint(atl[bo1]);
                        mma8(acc[nt], ah0, ah1, ah2, ah3, bh0, bh1);
                        mma8(acc[nt], ah0, ah1, ah2, ah3, bl0, bl1);
                        mma8(acc[nt], al0, al1, al2, al3, bh0, bh1);
                    }
                }
            }
        }
        // contraction: w2[t] += a2u[s,t] * Y[s,t]
        int s0 = s_base + wid * 16 + g;
        int s1 = s0 + 8;
#pragma unroll
        for (int nt = 0; nt < 8; ++nt) {
            int col = nt * 8 + 2 * tg;
            float2 h0 = *(const float2*)&aH[(size_t)s0 * NT + col];
            float2 l0 = *(const float2*)&aL[(size_t)s0 * NT + col];
            float2 h1 = *(const float2*)&aH[(size_t)s1 * NT + col];
            float2 l1 = *(const float2*)&aL[(size_t)s1 * NT + col];
            w2acc[nt * 2 + 0] += (h0.x + l0.x) * acc[nt][0] + (h1.x + l1.x) * acc[nt][2];
            w2acc[nt * 2 + 1] += (h0.y + l0.y) * acc[nt][1] + (h1.y + l1.y) * acc[nt][3];
        }
    }
#pragma unroll
    for (int i = 0; i < 16; ++i) {
        float v = w2acc[i];
        v += __shfl_xor_sync(0xffffffffu, v, 4);
        v += __shfl_xor_sync(0xffffffffu, v, 8);
        v += __shfl_xor_sync(0xffffffffu, v, 16);
        w2acc[i] = v;
    }
    __syncthreads();
    if (g == 0) {
#pragma unroll
        for (int i = 0; i < 16; ++i) {
            int col = (i >> 1) * 8 + 2 * tg + (i & 1);
            w2red[wid * 64 + col] = w2acc[i];
        }
    }
    __syncthreads();
    if (tid < 64) {
        float s = 0.f;
#pragma unroll
        for (int w = 0; w < 8; ++w) s += w2red[w * 64 + tid];
        g_w2[p * 64 + tid] = s;
    }
}

// ================= finalizers =================
__global__ void csim_kernel(const int* __restrict__ caps) {
    int p = blockIdx.x, b = p % NB, c = p / NB;
    int t = threadIdx.x;
    float cs = g_cols[p * 64 + t];
    float ci = 1.f / cs;
    float w12 = g_w12[p * 64 + t] * ci;
    float w2 = ci * sqrtf(fmaxf(g_w2[p * 64 + t], 0.f));
    float w1 = g_w1n[c * 64 + t];
    float sim = w12 / fmaxf(w1 * w2, EPSV);
    float row = (t < caps[c]) ? __expf(TEMP2 * sim) : 0.f;
#pragma unroll
    for (int o = 16; o; o >>= 1) row += __shfl_xor_sync(0xffffffffu, row, o);
    __shared__ float sred[2];
    if ((t & 31) == 0) sred[t >> 5] = row;
    __syncthreads();
    if (t == 0) g_sims[b * NB + c] = TEMP3 * logf(sred[0] + sred[1]);
}

__global__ void att_kernel(float* __restrict__ ao) {
    int b = blockIdx.x;
    int p = b * NB + b;
    int tid = threadIdx.x;
    __shared__ float ci[64];
    if (tid < 64) ci[tid] = 1.f / g_cols[p * 64 + tid];
    __syncthreads();
    const float* aH = g_a2uH + (size_t)p * SPAD * NT;
    const float* aL = g_a2uL + (size_t)p * SPAD * NT;
    for (int i = tid; i < NS * NT; i += 256) {
        int s = i >> 6, t = i & 63;
        ao[((size_t)b * NT + t) * NS + s] =
            (aH[(size_t)s * NT + t] + aL[(size_t)s * NT + t]) * ci[t];
    }
}

__global__ void loss_kernel(float* __restrict__ out) {
    __shared__ float part[4][NB];
    int i = threadIdx.x;
    if (i < NB) {
        const float* Ms = g_sims;
        const float* Mg = g_sc0;
        float m, sum;
        m = -INFINITY;
        for (int j = 0; j < NB; ++j) m = fmaxf(m, Ms[i * NB + j]);
        sum = 0.f;
        for (int j = 0; j < NB; ++j) sum += expf(Ms[i * NB + j] - m);
        part[0][i] = m + logf(sum) - Ms[i * NB + i];
        m = -INFINITY;
        for (int j = 0; j < NB; ++j) m = fmaxf(m, Ms[j * NB + i]);
        sum = 0.f;
        for (int j = 0; j < NB; ++j) sum += expf(Ms[j * NB + i] - m);
        part[1][i] = m + logf(sum) - Ms[i * NB + i];
        m = -INFINITY;
        for (int j = 0; j < NB; ++j) m = fmaxf(m, Mg[i * NB + j]);
        sum = 0.f;
        for (int j = 0; j < NB; ++j) sum += expf(Mg[i * NB + j] - m);
        part[2][i] = m + logf(sum) - Mg[i * NB + i];
        m = -INFINITY;
        for (int j = 0; j < NB; ++j) m = fmaxf(m, Mg[j * NB + i]);
        sum = 0.f;
        for (int j = 0; j < NB; ++j) sum += expf(Mg[j * NB + i] - m);
        part[3][i] = m + logf(sum) - Mg[i * NB + i];
    }
    __syncthreads();
    if (i == 0) {
        float l = 0.f;
        for (int k = 0; k < 4; ++k) {
            float s = 0.f;
            for (int j = 0; j < NB; ++j) s += part[k][j];
            l += s * (1.f / (float)NB);
        }
        out[0] = l;
    }
}

// ================= launch =================
extern "C" void kernel_launch(void* const* d_in, const int* in_sizes, int n_in,
                              void* d_out, int out_size) {
    const float* gfeat  = (const float*)d_in[0];
    const float* localf = (const float*)d_in[1];
    const float* words  = (const float*)d_in[2];
    const float* sfeat  = (const float*)d_in[3];
    const int*   caps   = (const int*)d_in[4];
    float* out = (float*)d_out;

    cudaFuncSetAttribute(scoreA_kernel, cudaFuncAttributeMaxDynamicSharedMemorySize, A_SMEM);
    cudaFuncSetAttribute(w2B_kernel, cudaFuncAttributeMaxDynamicSharedMemorySize, B_SMEM);

    size_t n_pad = (size_t)NB * NC * SPAD;
    pad_kernel<<<(unsigned)((n_pad + 255) / 256), 256>>>(localf);
    gram_kernel<<<dim3(6, NB), 256>>>();
    prep_G<<<(unsigned)(((size_t)NB * SPAD * SPAD + 255) / 256), 256>>>();
    prep_ctx<<<(unsigned)((n_pad + 255) / 256), 256>>>(localf);
    prep_w<<<(unsigned)(((size_t)NB * NC * NT + 255) / 256), 256>>>(words);

    norms_kernel<<<NB, 64>>>(words, gfeat, sfeat);
    gscore_kernel<<<NB, 256>>>(gfeat, sfeat);

    scoreA_kernel<<<NPAIR, 256, A_SMEM>>>(caps);
    w2B_kernel<<<NPAIR, 256, B_SMEM>>>(caps);
    csim_kernel<<<NPAIR, 64>>>(caps);

    int wa = (out_size >= 1 + NB * NT * NS) ? 1 : 0;
    if (wa) att_kernel<<<NB, 256>>>(out + 1);
    loss_kernel<<<1, 64>>>(out);
}

// round 11
// speedup vs baseline: 2.1280x; 1.7451x over previous
#include <cuda_runtime.h>
#include <cuda_bf16.h>
#include <math.h>
#include <stdint.h>

#define NB 48
#define NC 768
#define NS 361
#define NT 64
#define SPAD 384
#define ND2 (NC / 2)    // 384 k-pairs over C
#define NS2 (SPAD / 2)  // 192 k-pairs over S
#define NPAIR (NB * NB)

#define TEMP1 4.0f
#define TEMP2 5.0f
#define TEMP3 10.0f
#define EPSV  1e-8f

typedef unsigned long long ull;

// ================= device scratch =================
__device__ float g_ctxp[(size_t)NB * NC * SPAD];     // padded ctx [b][d][384] (gram)
__device__ float g_G[(size_t)NB * SPAD * SPAD];      // fp32 Gram
__device__ uint32_t g_ctxPH[(size_t)NB * ND2 * SPAD]; // bf16x2 hi ctx [b][d2][s]
__device__ uint32_t g_ctxPL[(size_t)NB * ND2 * SPAD];
__device__ uint32_t g_wPH[(size_t)NB * ND2 * NT];     // bf16x2 hi words [c][d2][t]
__device__ uint32_t g_wPL[(size_t)NB * ND2 * NT];
__device__ uint32_t g_GPH[(size_t)NB * NS2 * SPAD];   // bf16x2 hi G [b][k2][s]
__device__ uint32_t g_GPL[(size_t)NB * NS2 * SPAD];
__device__ float g_a2u[(size_t)NPAIR * SPAD * NT];    // fp32 a2u [p][s][t]
__device__ uint32_t g_aPH[(size_t)NPAIR * NS2 * NT];  // bf16x2 hi a2u [p][s2][t]
__device__ uint32_t g_aPL[(size_t)NPAIR * NS2 * NT];
__device__ float g_cols[NPAIR * NT];
__device__ float g_w12[NPAIR * NT];
__device__ float g_w2[NPAIR * NT];
__device__ float g_w1n[NB * NT];
__device__ float g_gn[NB];
__device__ float g_sn[NB];
__device__ float g_sc0[NB * NB];
__device__ float g_sims[NB * NB];

// ================= helpers =================
__device__ __forceinline__ uint32_t packbf(float v0, float v1, uint32_t& lo) {
    __nv_bfloat16 h0 = __float2bfloat16(v0);
    __nv_bfloat16 h1 = __float2bfloat16(v1);
    __nv_bfloat16 l0 = __float2bfloat16(v0 - __bfloat162float(h0));
    __nv_bfloat16 l1 = __float2bfloat16(v1 - __bfloat162float(h1));
    lo = (uint32_t)__bfloat16_as_ushort(l0) | ((uint32_t)__bfloat16_as_ushort(l1) << 16);
    return (uint32_t)__bfloat16_as_ushort(h0) | ((uint32_t)__bfloat16_as_ushort(h1) << 16);
}
__device__ __forceinline__ void mma16(float* c, uint32_t a0, uint32_t a1,
                                      uint32_t a2, uint32_t a3,
                                      uint32_t b0, uint32_t b1) {
    asm volatile(
        "mma.sync.aligned.m16n8k16.row.col.f32.bf16.bf16.f32 "
        "{%0,%1,%2,%3}, {%4,%5,%6,%7}, {%8,%9}, {%0,%1,%2,%3};"
        : "+f"(c[0]), "+f"(c[1]), "+f"(c[2]), "+f"(c[3])
        : "r"(a0), "r"(a1), "r"(a2), "r"(a3), "r"(b0), "r"(b1));
}
__device__ __forceinline__ uint32_t smem_u32(const void* p) {
    uint32_t a;
    asm("{ .reg .u64 t; cvta.to.shared.u64 t, %1; cvt.u32.u64 %0, t; }"
        : "=r"(a) : "l"(p));
    return a;
}
__device__ __forceinline__ void cpa16(uint32_t dst, const void* src) {
    asm volatile("cp.async.cg.shared.global [%0], [%1], 16;"
                 :: "r"(dst), "l"(src));
}
#define CPA_COMMIT() asm volatile("cp.async.commit_group;")
#define CPA_WAIT0()  asm volatile("cp.async.wait_group 0;")

// ================= prep kernels =================
__global__ void pad_kernel(const float* __restrict__ lf) {
    size_t i = (size_t)blockIdx.x * blockDim.x + threadIdx.x;
    if (i < (size_t)NB * NC * SPAD) {
        int x = (int)(i % SPAD);
        size_t r = i / SPAD;
        g_ctxp[i] = (x < NS) ? lf[r * NS + x] : 0.f;
    }
}
__global__ void prep_ctxP(const float* __restrict__ lf) {
    size_t i = (size_t)blockIdx.x * blockDim.x + threadIdx.x;
    if (i >= (size_t)NB * ND2 * SPAD) return;
    int s = (int)(i % SPAD);
    size_t r = i / SPAD;
    int d2 = (int)(r % ND2);
    int b = (int)(r / ND2);
    float v0 = 0.f, v1 = 0.f;
    if (s < NS) {
        v0 = lf[((size_t)b * NC + 2 * d2) * NS + s];
        v1 = lf[((size_t)b * NC + 2 * d2 + 1) * NS + s];
    }
    uint32_t lo;
    g_ctxPH[i] = packbf(v0, v1, lo);
    g_ctxPL[i] = lo;
}
__global__ void prep_wP(const float* __restrict__ w) {
    size_t i = (size_t)blockIdx.x * blockDim.x + threadIdx.x;
    if (i >= (size_t)NB * ND2 * NT) return;
    int t = (int)(i % NT);
    size_t r = i / NT;
    int d2 = (int)(r % ND2);
    int c = (int)(r / ND2);
    float v0 = w[((size_t)c * NC + 2 * d2) * NT + t];
    float v1 = w[((size_t)c * NC + 2 * d2 + 1) * NT + t];
    uint32_t lo;
    g_wPH[i] = packbf(v0, v1, lo);
    g_wPL[i] = lo;
}
__global__ void prep_GP() {
    size_t i = (size_t)blockIdx.x * blockDim.x + threadIdx.x;
    if (i >= (size_t)NB * NS2 * SPAD) return;
    int s = (int)(i % SPAD);
    size_t r = i / SPAD;
    int k2 = (int)(r % NS2);
    int b = (int)(r / NS2);
    float v0 = g_G[((size_t)b * SPAD + 2 * k2) * SPAD + s];
    float v1 = g_G[((size_t)b * SPAD + 2 * k2 + 1) * SPAD + s];
    uint32_t lo;
    g_GPH[i] = packbf(v0, v1, lo);
    g_GPL[i] = lo;
}
__global__ void prep_aP() {
    size_t i = (size_t)blockIdx.x * blockDim.x + threadIdx.x;
    if (i >= (size_t)NPAIR * NS2 * NT) return;
    int t = (int)(i % NT);
    size_t r = i / NT;
    int s2 = (int)(r % NS2);
    int p = (int)(r / NS2);
    float v0 = g_a2u[((size_t)p * SPAD + 2 * s2) * NT + t];
    float v1 = g_a2u[((size_t)p * SPAD + 2 * s2 + 1) * NT + t];
    uint32_t lo;
    g_aPH[i] = packbf(v0, v1, lo);
    g_aPL[i] = lo;
}

// ================= gram (FFMA f32x2) =================
__device__ __forceinline__ ull pack2s(float x) {
    ull r; asm("mov.b64 %0, {%1, %1};" : "=l"(r) : "f"(x)); return r;
}
__device__ __forceinline__ void ffma2(ull& d, ull a, ull b) {
    asm("fma.rn.f32x2 %0, %1, %2, %0;" : "+l"(d) : "l"(a), "l"(b));
}
__device__ __forceinline__ void unpack2(float& lo, float& hi, ull v) {
    asm("mov.b64 {%0, %1}, %2;" : "=f"(lo), "=f"(hi) : "l"(v));
}
__device__ __forceinline__ void fma8x8p(ull (&acc)[8][4],
                                        const float4 a0, const float4 a1,
                                        const ulonglong2 b01, const ulonglong2 b23) {
    float av[8] = {a0.x, a0.y, a0.z, a0.w, a1.x, a1.y, a1.z, a1.w};
    ull bp[4] = {b01.x, b01.y, b23.x, b23.y};
#pragma unroll
    for (int i = 0; i < 8; ++i) {
        ull ap = pack2s(av[i]);
        ffma2(acc[i][0], ap, bp[0]);
        ffma2(acc[i][1], ap, bp[1]);
        ffma2(acc[i][2], ap, bp[2]);
        ffma2(acc[i][3], ap, bp[3]);
    }
}

__global__ __launch_bounds__(256) void gram_kernel() {
    const int byA[6] = {0, 0, 0, 1, 1, 2};
    const int bxA[6] = {0, 1, 2, 1, 2, 2};
    int p = blockIdx.x, b = blockIdx.y;
    int i0 = byA[p] * 128, j0 = bxA[p] * 128;
    __shared__ float At[32 * 128];
    __shared__ float Bt[32 * 128];
    const float* cp = g_ctxp + (size_t)b * NC * SPAD;
    int tid = threadIdx.x;
    int ti = tid & 15, si = tid >> 4;
    int il = si * 8, jl = ti * 8;
    ull acc[8][4] = {};
    for (int kc = 0; kc < 24; ++kc) {
        int k0 = kc * 32;
        __syncthreads();
        for (int i4 = tid; i4 < 1024; i4 += 256) {
            int kk = i4 >> 5, x4 = i4 & 31;
            const float* base = cp + (size_t)(k0 + kk) * SPAD;
            ((float4*)At)[i4] = *(const float4*)(base + i0 + x4 * 4);
            ((float4*)Bt)[i4] = *(const float4*)(base + j0 + x4 * 4);
        }
        __syncthreads();
#pragma unroll 4
        for (int k = 0; k < 32; ++k) {
            float4 a0 = *(const float4*)&At[k * 128 + il];
            float4 a1 = *(const float4*)&At[k * 128 + il + 4];
            ulonglong2 b01 = *(const ulonglong2*)&Bt[k * 128 + jl];
            ulonglong2 b23 = *(const ulonglong2*)&Bt[k * 128 + jl + 4];
            fma8x8p(acc, a0, a1, b01, b23);
        }
    }
    float c[8][8];
#pragma unroll
    for (int ii = 0; ii < 8; ++ii)
#pragma unroll
        for (int j = 0; j < 4; ++j)
            unpack2(c[ii][2 * j], c[ii][2 * j + 1], acc[ii][j]);
    float* Gb = g_G + (size_t)b * SPAD * SPAD;
#pragma unroll
    for (int ii = 0; ii < 8; ++ii) {
        int row = i0 + il + ii;
        *(float4*)&Gb[(size_t)row * SPAD + j0 + jl] =
            make_float4(c[ii][0], c[ii][1], c[ii][2], c[ii][3]);
        *(float4*)&Gb[(size_t)row * SPAD + j0 + jl + 4] =
            make_float4(c[ii][4], c[ii][5], c[ii][6], c[ii][7]);
    }
    if (i0 != j0) {
#pragma unroll
        for (int jj = 0; jj < 8; ++jj) {
            int row = j0 + jl + jj;
#pragma unroll
            for (int ii = 0; ii < 8; ++ii)
                Gb[(size_t)row * SPAD + i0 + il + ii] = c[ii][jj];
        }
    }
}

// ================= norms / gscore =================
__global__ void norms_kernel(const float* __restrict__ words,
                             const float* __restrict__ gfeat,
                             const float* __restrict__ sfeat) {
    int c = blockIdx.x;
    int tid = threadIdx.x;
    float s = 0.f;
    for (int d = 0; d < NC; ++d) {
        float v = words[((size_t)c * NC + d) * NT + tid];
        s = fmaf(v, v, s);
    }
    g_w1n[c * NT + tid] = sqrtf(s);
    float a = 0.f, bb = 0.f;
    for (int d = tid; d < NC; d += 64) {
        float v = gfeat[(size_t)c * NC + d];
        float w = sfeat[(size_t)c * NC + d];
        a = fmaf(v, v, a);
        bb = fmaf(w, w, bb);
    }
#pragma unroll
    for (int o = 16; o; o >>= 1) {
        a  += __shfl_xor_sync(0xffffffffu, a, o);
        bb += __shfl_xor_sync(0xffffffffu, bb, o);
    }
    __shared__ float r[4];
    int warp = tid >> 5, lane = tid & 31;
    if (lane == 0) { r[warp] = a; r[2 + warp] = bb; }
    __syncthreads();
    if (tid == 0) {
        g_gn[c] = sqrtf(r[0] + r[1]);
        g_sn[c] = sqrtf(r[2] + r[3]);
    }
}

__global__ void gscore_kernel(const float* __restrict__ gfeat,
                              const float* __restrict__ sfeat) {
    int i = blockIdx.x;
    int tid = threadIdx.x;
    int warp = tid >> 5, lane = tid & 31;
    for (int j = warp; j < NB; j += 8) {
        float acc = 0.f;
        for (int d = lane; d < NC; d += 32)
            acc = fmaf(gfeat[(size_t)i * NC + d], sfeat[(size_t)j * NC + d], acc);
#pragma unroll
        for (int o = 16; o; o >>= 1) acc += __shfl_xor_sync(0xffffffffu, acc, o);
        if (lane == 0) {
            float denom = fmaxf(g_gn[i] * g_sn[j], EPSV);
            g_sc0[i * NB + j] = TEMP3 * acc / denom;
        }
    }
}

// ================= Kernel A: bf16 mma scores + fused softmax =================
// smem u32 tiles: A [32 kpair][132], B [32 kpair][68]
#define A_CTH 0
#define A_CTL 16896
#define A_WTH 33792
#define A_WTL 42496
#define A_REDC 51200
#define A_REDW 53248
#define A_SMEM 55296

__global__ __launch_bounds__(256, 2) void scoreA_kernel(const int* __restrict__ caps) {
    extern __shared__ char smc[];
    uint32_t smb = smem_u32(smc);
    uint32_t* cth = (uint32_t*)(smc + A_CTH);
    uint32_t* ctl = (uint32_t*)(smc + A_CTL);
    uint32_t* wth = (uint32_t*)(smc + A_WTH);
    uint32_t* wtl = (uint32_t*)(smc + A_WTL);
    float* redc = (float*)(smc + A_REDC);
    float* redw = (float*)(smc + A_REDW);

    int tid = threadIdx.x, wid = tid >> 5, lane = tid & 31;
    int g = lane >> 2, tg = lane & 3;
    int p = blockIdx.x, b = p % NB, c = p / NB;
    const uint32_t* cH = g_ctxPH + (size_t)b * ND2 * SPAD;
    const uint32_t* cL = g_ctxPL + (size_t)b * ND2 * SPAD;
    const uint32_t* wHp = g_wPH + (size_t)c * ND2 * NT;
    const uint32_t* wLp = g_wPL + (size_t)c * ND2 * NT;
    int cap = caps[c];
    int capN = (cap + 7) >> 3;
    int bsegs = 2 * capN;     // 16B segments per B-tile row

    float colacc[16] = {}, w12acc[16] = {};
    float* au = g_a2u + (size_t)p * SPAD * NT;

    for (int st = 0; st < 3; ++st) {
        int s_base = st * 128;
        float acc[8][4] = {};
        for (int kc = 0; kc < 12; ++kc) {
            int k0 = kc * 32;   // kpair base
            __syncthreads();
            // A tiles (hi+lo): 2048 segs (32 rows x 32 segs x 2 planes)
            for (int i = tid; i < 2048; i += 256) {
                int h = i >> 10;
                int j = i & 1023;
                int kk = j >> 5, x4 = j & 31;
                const uint32_t* src = (h ? cL : cH) + (size_t)(k0 + kk) * SPAD + s_base + x4 * 4;
                cpa16(smb + (h ? A_CTL : A_CTH) + (uint32_t)(kk * 132 + x4 * 4) * 4, src);
            }
            // B tiles (hi+lo): 32 rows x bsegs x 2 planes
            int btot = 64 * bsegs;
            for (int i = tid; i < btot; i += 256) {
                int h = (i >= 32 * bsegs);
                int j = h ? i - 32 * bsegs : i;
                int kk = j / bsegs, x4 = j - kk * bsegs;
                const uint32_t* src = (h ? wLp : wHp) + (size_t)(k0 + kk) * NT + x4 * 4;
                cpa16(smb + (h ? A_WTL : A_WTH) + (uint32_t)(kk * 68 + x4 * 4) * 4, src);
            }
            CPA_COMMIT();
            CPA_WAIT0();
            __syncthreads();
            int arow = wid * 16 + g;
#pragma unroll
            for (int j = 0; j < 4; ++j) {
                int jb = j * 8;
                int r0 = (jb + tg) * 132 + arow;
                int r1 = (jb + tg + 4) * 132 + arow;
                uint32_t ah0 = cth[r0], ah1 = cth[r0 + 8];
                uint32_t ah2 = cth[r1], ah3 = cth[r1 + 8];
                uint32_t al0 = ctl[r0], al1 = ctl[r0 + 8];
                uint32_t al2 = ctl[r1], al3 = ctl[r1 + 8];
#pragma unroll
                for (int nt = 0; nt < 8; ++nt) {
                    if (nt < capN) {
                        int b0i = (jb + tg) * 68 + nt * 8 + g;
                        int b1i = (jb + tg + 4) * 68 + nt * 8 + g;
                        uint32_t bh0 = wth[b0i], bh1 = wth[b1i];
                        uint32_t bl0 = wtl[b0i], bl1 = wtl[b1i];
                        mma16(acc[nt], ah0, ah1, ah2, ah3, bh0, bh1);
                        mma16(acc[nt], ah0, ah1, ah2, ah3, bl0, bl1);
                        mma16(acc[nt], al0, al1, al2, al3, bh0, bh1);
                    }
                }
            }
        }
        // ---- fused masked softmax over t ----
        int s0 = s_base + wid * 16 + g;
        int s1 = s0 + 8;
        float mx0 = -1e30f, mx1 = -1e30f;
#pragma unroll
        for (int nt = 0; nt < 8; ++nt) {
            int col = nt * 8 + 2 * tg;
            if (col < cap)     { mx0 = fmaxf(mx0, acc[nt][0]); mx1 = fmaxf(mx1, acc[nt][2]); }
            if (col + 1 < cap) { mx0 = fmaxf(mx0, acc[nt][1]); mx1 = fmaxf(mx1, acc[nt][3]); }
        }
        mx0 = fmaxf(mx0, __shfl_xor_sync(0xffffffffu, mx0, 1));
        mx0 = fmaxf(mx0, __shfl_xor_sync(0xffffffffu, mx0, 2));
        mx1 = fmaxf(mx1, __shfl_xor_sync(0xffffffffu, mx1, 1));
        mx1 = fmaxf(mx1, __shfl_xor_sync(0xffffffffu, mx1, 2));
        float sm0 = 0.f, sm1 = 0.f;
#pragma unroll
        for (int nt = 0; nt < 8; ++nt) {
            int col = nt * 8 + 2 * tg;
            if (col < cap)     { sm0 += __expf(acc[nt][0] - mx0); sm1 += __expf(acc[nt][2] - mx1); }
            if (col + 1 < cap) { sm0 += __expf(acc[nt][1] - mx0); sm1 += __expf(acc[nt][3] - mx1); }
        }
        sm0 += __shfl_xor_sync(0xffffffffu, sm0, 1);
        sm0 += __shfl_xor_sync(0xffffffffu, sm0, 2);
        sm1 += __shfl_xor_sync(0xffffffffu, sm1, 1);
        sm1 += __shfl_xor_sync(0xffffffffu, sm1, 2);
        float inv0 = 1.f / sm0, inv1 = 1.f / sm1;
        bool v0ok = (s0 < NS), v1ok = (s1 < NS);
#pragma unroll
        for (int nt = 0; nt < 8; ++nt) {
            int col = nt * 8 + 2 * tg;
            float e00 = (col < cap)     ? __expf(acc[nt][0] - mx0) : 0.f;
            float e01 = (col + 1 < cap) ? __expf(acc[nt][1] - mx0) : 0.f;
            float e10 = (col < cap)     ? __expf(acc[nt][2] - mx1) : 0.f;
            float e11 = (col + 1 < cap) ? __expf(acc[nt][3] - mx1) : 0.f;
            float u00 = __expf(TEMP1 * (e00 * inv0));
            float u01 = __expf(TEMP1 * (e01 * inv0));
            float u10 = __expf(TEMP1 * (e10 * inv1));
            float u11 = __expf(TEMP1 * (e11 * inv1));
            float a00 = v0ok ? u00 : 0.f, a01 = v0ok ? u01 : 0.f;
            float a10 = v1ok ? u10 : 0.f, a11 = v1ok ? u11 : 0.f;
            colacc[nt * 2 + 0] += a00 + a10;
            colacc[nt * 2 + 1] += a01 + a11;
            w12acc[nt * 2 + 0] += (v0ok ? u00 * acc[nt][0] : 0.f) + (v1ok ? u10 * acc[nt][2] : 0.f);
            w12acc[nt * 2 + 1] += (v0ok ? u01 * acc[nt][1] : 0.f) + (v1ok ? u11 * acc[nt][3] : 0.f);
            *(float2*)&au[(size_t)s0 * NT + col] = make_float2(a00, a01);
            *(float2*)&au[(size_t)s1 * NT + col] = make_float2(a10, a11);
        }
    }
#pragma unroll
    for (int i = 0; i < 16; ++i) {
        float v = colacc[i], w = w12acc[i];
        v += __shfl_xor_sync(0xffffffffu, v, 4);
        v += __shfl_xor_sync(0xffffffffu, v, 8);
        v += __shfl_xor_sync(0xffffffffu, v, 16);
        w += __shfl_xor_sync(0xffffffffu, w, 4);
        w += __shfl_xor_sync(0xffffffffu, w, 8);
        w += __shfl_xor_sync(0xffffffffu, w, 16);
        colacc[i] = v; w12acc[i] = w;
    }
    __syncthreads();
    if (g == 0) {
#pragma unroll
        for (int i = 0; i < 16; ++i) {
            int col = (i >> 1) * 8 + 2 * tg + (i & 1);
            redc[wid * 64 + col] = colacc[i];
            redw[wid * 64 + col] = w12acc[i];
        }
    }
    __syncthreads();
    if (tid < 64) {
        float cs = 0.f, ws = 0.f;
#pragma unroll
        for (int w = 0; w < 8; ++w) { cs += redc[w * 64 + tid]; ws += redw[w * 64 + tid]; }
        g_cols[p * 64 + tid] = cs;
        g_w12[p * 64 + tid] = ws;
    }
}

// ================= Kernel B: bf16 mma Gram quadratic form =================
#define B_CTH 0
#define B_CTL 16896
#define B_ATH 33792
#define B_ATL 42496
#define B_W2R 51200
#define B_SMEM 53248

__global__ __launch_bounds__(256, 2) void w2B_kernel(const int* __restrict__ caps) {
    extern __shared__ char smc[];
    uint32_t smb = smem_u32(smc);
    uint32_t* cth = (uint32_t*)(smc + B_CTH);
    uint32_t* ctl = (uint32_t*)(smc + B_CTL);
    uint32_t* ath = (uint32_t*)(smc + B_ATH);
    uint32_t* atl = (uint32_t*)(smc + B_ATL);
    float* w2red = (float*)(smc + B_W2R);

    int tid = threadIdx.x, wid = tid >> 5, lane = tid & 31;
    int g = lane >> 2, tg = lane & 3;
    int p = blockIdx.x, b = p % NB, c = p / NB;
    const uint32_t* GHp = g_GPH + (size_t)b * NS2 * SPAD;
    const uint32_t* GLp = g_GPL + (size_t)b * NS2 * SPAD;
    const uint32_t* aHp = g_aPH + (size_t)p * NS2 * NT;
    const uint32_t* aLp = g_aPL + (size_t)p * NS2 * NT;
    const float* au = g_a2u + (size_t)p * SPAD * NT;
    int cap = caps[c];
    int capN = (cap + 7) >> 3;
    int bsegs = 2 * capN;

    float w2acc[16] = {};

    for (int st = 0; st < 3; ++st) {
        int s_base = st * 128;
        float acc[8][4] = {};
        for (int kc = 0; kc < 6; ++kc) {
            int k0 = kc * 32;   // kpair base (0..191)
            __syncthreads();
            for (int i = tid; i < 2048; i += 256) {
                int h = i >> 10;
                int j = i & 1023;
                int kk = j >> 5, x4 = j & 31;
                const uint32_t* src = (h ? GLp : GHp) + (size_t)(k0 + kk) * SPAD + s_base + x4 * 4;
                cpa16(smb + (h ? B_CTL : B_CTH) + (uint32_t)(kk * 132 + x4 * 4) * 4, src);
            }
            int btot = 64 * bsegs;
            for (int i = tid; i < btot; i += 256) {
                int h = (i >= 32 * bsegs);
                int j = h ? i - 32 * bsegs : i;
                int kk = j / bsegs, x4 = j - kk * bsegs;
                const uint32_t* src = (h ? aLp : aHp) + (size_t)(k0 + kk) * NT + x4 * 4;
                cpa16(smb + (h ? B_ATL : B_ATH) + (uint32_t)(kk * 68 + x4 * 4) * 4, src);
            }
            CPA_COMMIT();
            CPA_WAIT0();
            __syncthreads();
            int arow = wid * 16 + g;
#pragma unroll
            for (int j = 0; j < 4; ++j) {
                int jb = j * 8;
                int r0 = (jb + tg) * 132 + arow;
                int r1 = (jb + tg + 4) * 132 + arow;
                uint32_t ah0 = cth[r0], ah1 = cth[r0 + 8];
                uint32_t ah2 = cth[r1], ah3 = cth[r1 + 8];
                uint32_t al0 = ctl[r0], al1 = ctl[r0 + 8];
                uint32_t al2 = ctl[r1], al3 = ctl[r1 + 8];
#pragma unroll
                for (int nt = 0; nt < 8; ++nt) {
                    if (nt < capN) {
                        int b0i = (jb + tg) * 68 + nt * 8 + g;
                        int b1i = (jb + tg + 4) * 68 + nt * 8 + g;
                        uint32_t bh0 = ath[b0i], bh1 = ath[b1i];
                        uint32_t bl0 = atl[b0i], bl1 = atl[b1i];
                        mma16(acc[nt], ah0, ah1, ah2, ah3, bh0, bh1);
                        mma16(acc[nt], ah0, ah1, ah2, ah3, bl0, bl1);
                        mma16(acc[nt], al0, al1, al2, al3, bh0, bh1);
                    }
                }
            }
        }
        // contraction: w2[t] += a2u[s,t] * Y[s,t]
        int s0 = s_base + wid * 16 + g;
        int s1 = s0 + 8;
#pragma unroll
        for (int nt = 0; nt < 8; ++nt) {
            int col = nt * 8 + 2 * tg;
            float2 a0v = *(const float2*)&au[(size_t)s0 * NT + col];
            float2 a1v = *(const float2*)&au[(size_t)s1 * NT + col];
            w2acc[nt * 2 + 0] += a0v.x * acc[nt][0] + a1v.x * acc[nt][2];
            w2acc[nt * 2 + 1] += a0v.y * acc[nt][1] + a1v.y * acc[nt][3];
        }
    }
#pragma unroll
    for (int i = 0; i < 16; ++i) {
        float v = w2acc[i];
        v += __shfl_xor_sync(0xffffffffu, v, 4);
        v += __shfl_xor_sync(0xffffffffu, v, 8);
        v += __shfl_xor_sync(0xffffffffu, v, 16);
        w2acc[i] = v;
    }
    __syncthreads();
    if (g == 0) {
#pragma unroll
        for (int i = 0; i < 16; ++i) {
            int col = (i >> 1) * 8 + 2 * tg + (i & 1);
            w2red[wid * 64 + col] = w2acc[i];
        }
    }
    __syncthreads();
    if (tid < 64) {
        float s = 0.f;
#pragma unroll
        for (int w = 0; w < 8; ++w) s += w2red[w * 64 + tid];
        g_w2[p * 64 + tid] = s;
    }
}

// ================= finalizers =================
__global__ void csim_kernel(const int* __restrict__ caps) {
    int p = blockIdx.x, b = p % NB, c = p / NB;
    int t = threadIdx.x;
    float cs = g_cols[p * 64 + t];
    float ci = 1.f / cs;
    float w12 = g_w12[p * 64 + t] * ci;
    float w2 = ci * sqrtf(fmaxf(g_w2[p * 64 + t], 0.f));
    float w1 = g_w1n[c * 64 + t];
    float sim = w12 / fmaxf(w1 * w2, EPSV);
    float row = (t < caps[c]) ? __expf(TEMP2 * sim) : 0.f;
#pragma unroll
    for (int o = 16; o; o >>= 1) row += __shfl_xor_sync(0xffffffffu, row, o);
    __shared__ float sred[2];
    if ((t & 31) == 0) sred[t >> 5] = row;
    __syncthreads();
    if (t == 0) g_sims[b * NB + c] = TEMP3 * logf(sred[0] + sred[1]);
}

__global__ void att_kernel(float* __restrict__ ao) {
    int b = blockIdx.x;
    int p = b * NB + b;
    int tid = threadIdx.x;
    __shared__ float ci[64];
    if (tid < 64) ci[tid] = 1.f / g_cols[p * 64 + tid];
    __syncthreads();
    const float* au = g_a2u + (size_t)p * SPAD * NT;
    for (int i = tid; i < NS * NT; i += 256) {
        int s = i >> 6, t = i & 63;
        ao[((size_t)b * NT + t) * NS + s] = au[(size_t)s * NT + t] * ci[t];
    }
}

__global__ void loss_kernel(float* __restrict__ out) {
    __shared__ float part[4][NB];
    int i = threadIdx.x;
    if (i < NB) {
        const float* Ms = g_sims;
        const float* Mg = g_sc0;
        float m, sum;
        m = -INFINITY;
        for (int j = 0; j < NB; ++j) m = fmaxf(m, Ms[i * NB + j]);
        sum = 0.f;
        for (int j = 0; j < NB; ++j) sum += expf(Ms[i * NB + j] - m);
        part[0][i] = m + logf(sum) - Ms[i * NB + i];
        m = -INFINITY;
        for (int j = 0; j < NB; ++j) m = fmaxf(m, Ms[j * NB + i]);
        sum = 0.f;
        for (int j = 0; j < NB; ++j) sum += expf(Ms[j * NB + i] - m);
        part[1][i] = m + logf(sum) - Ms[i * NB + i];
        m = -INFINITY;
        for (int j = 0; j < NB; ++j) m = fmaxf(m, Mg[i * NB + j]);
        sum = 0.f;
        for (int j = 0; j < NB; ++j) sum += expf(Mg[i * NB + j] - m);
        part[2][i] = m + logf(sum) - Mg[i * NB + i];
        m = -INFINITY;
        for (int j = 0; j < NB; ++j) m = fmaxf(m, Mg[j * NB + i]);
        sum = 0.f;
        for (int j = 0; j < NB; ++j) sum += expf(Mg[j * NB + i] - m);
        part[3][i] = m + logf(sum) - Mg[i * NB + i];
    }
    __syncthreads();
    if (i == 0) {
        float l = 0.f;
        for (int k = 0; k < 4; ++k) {
            float s = 0.f;
            for (int j = 0; j < NB; ++j) s += part[k][j];
            l += s * (1.f / (float)NB);
        }
        out[0] = l;
    }
}

// ================= launch =================
extern "C" void kernel_launch(void* const* d_in, const int* in_sizes, int n_in,
                              void* d_out, int out_size) {
    const float* gfeat  = (const float*)d_in[0];
    const float* localf = (const float*)d_in[1];
    const float* words  = (const float*)d_in[2];
    const float* sfeat  = (const float*)d_in[3];
    const int*   caps   = (const int*)d_in[4];
    float* out = (float*)d_out;

    cudaFuncSetAttribute(scoreA_kernel, cudaFuncAttributeMaxDynamicSharedMemorySize, A_SMEM);
    cudaFuncSetAttribute(w2B_kernel, cudaFuncAttributeMaxDynamicSharedMemorySize, B_SMEM);

    size_t n_pad = (size_t)NB * NC * SPAD;
    pad_kernel<<<(unsigned)((n_pad + 255) / 256), 256>>>(localf);
    gram_kernel<<<dim3(6, NB), 256>>>();
    prep_GP<<<(unsigned)(((size_t)NB * NS2 * SPAD + 255) / 256), 256>>>();
    prep_ctxP<<<(unsigned)(((size_t)NB * ND2 * SPAD + 255) / 256), 256>>>(localf);
    prep_wP<<<(unsigned)(((size_t)NB * ND2 * NT + 255) / 256), 256>>>(words);

    norms_kernel<<<NB, 64>>>(words, gfeat, sfeat);
    gscore_kernel<<<NB, 256>>>(gfeat, sfeat);

    scoreA_kernel<<<NPAIR, 256, A_SMEM>>>(caps);
    prep_aP<<<(unsigned)(((size_t)NPAIR * NS2 * NT + 255) / 256), 256>>>();
    w2B_kernel<<<NPAIR, 256, B_SMEM>>>(caps);
    csim_kernel<<<NPAIR, 64>>>(caps);

    int wa = (out_size >= 1 + NB * NT * NS) ? 1 : 0;
    if (wa) att_kernel<<<NB, 256>>>(out + 1);
    loss_kernel<<<1, 64>>>(out);
}

// round 12
// speedup vs baseline: 2.1281x; 1.0000x over previous
#include <cuda_runtime.h>
#include <cuda_bf16.h>
#include <math.h>
#include <stdint.h>

#define NB 48
#define NC 768
#define NS 361
#define NT 64
#define SPAD 384
#define ND2 (NC / 2)    // 384 k-pairs over C
#define NS2 (SPAD / 2)  // 192 k-pairs over S
#define NPAIR (NB * NB)

#define TEMP1 4.0f
#define TEMP2 5.0f
#define TEMP3 10.0f
#define EPSV  1e-8f

typedef unsigned long long ull;

// ================= device scratch =================
__device__ float g_ctxp[(size_t)NB * NC * SPAD];     // padded ctx [b][d][384] (gram)
__device__ float g_G[(size_t)NB * SPAD * SPAD];      // fp32 Gram
__device__ uint32_t g_ctxPH[(size_t)NB * ND2 * SPAD]; // bf16x2 hi ctx [b][d2][s]
__device__ uint32_t g_ctxPL[(size_t)NB * ND2 * SPAD];
__device__ uint32_t g_wPH[(size_t)NB * ND2 * NT];     // bf16x2 hi words [c][d2][t]
__device__ uint32_t g_wPL[(size_t)NB * ND2 * NT];
__device__ uint32_t g_GPH[(size_t)NB * NS2 * SPAD];   // bf16x2 hi G [b][k2][s]
__device__ uint32_t g_GPL[(size_t)NB * NS2 * SPAD];
__device__ float g_a2u[(size_t)NPAIR * SPAD * NT];    // fp32 a2u [p][s][t]
__device__ uint32_t g_aPH[(size_t)NPAIR * NS2 * NT];  // bf16x2 hi a2u [p][s2][t]
__device__ uint32_t g_aPL[(size_t)NPAIR * NS2 * NT];
__device__ float g_cols[NPAIR * NT];
__device__ float g_w12[NPAIR * NT];
__device__ float g_w2[NPAIR * NT];
__device__ float g_w1n[NB * NT];
__device__ float g_gn[NB];
__device__ float g_sn[NB];
__device__ float g_sc0[NB * NB];
__device__ float g_sims[NB * NB];

// ================= helpers =================
__device__ __forceinline__ uint32_t packbf(float v0, float v1, uint32_t& lo) {
    __nv_bfloat16 h0 = __float2bfloat16(v0);
    __nv_bfloat16 h1 = __float2bfloat16(v1);
    __nv_bfloat16 l0 = __float2bfloat16(v0 - __bfloat162float(h0));
    __nv_bfloat16 l1 = __float2bfloat16(v1 - __bfloat162float(h1));
    lo = (uint32_t)__bfloat16_as_ushort(l0) | ((uint32_t)__bfloat16_as_ushort(l1) << 16);
    return (uint32_t)__bfloat16_as_ushort(h0) | ((uint32_t)__bfloat16_as_ushort(h1) << 16);
}
__device__ __forceinline__ void mma16(float* c, uint32_t a0, uint32_t a1,
                                      uint32_t a2, uint32_t a3,
                                      uint32_t b0, uint32_t b1) {
    asm volatile(
        "mma.sync.aligned.m16n8k16.row.col.f32.bf16.bf16.f32 "
        "{%0,%1,%2,%3}, {%4,%5,%6,%7}, {%8,%9}, {%0,%1,%2,%3};"
        : "+f"(c[0]), "+f"(c[1]), "+f"(c[2]), "+f"(c[3])
        : "r"(a0), "r"(a1), "r"(a2), "r"(a3), "r"(b0), "r"(b1));
}
__device__ __forceinline__ uint32_t smem_u32(const void* p) {
    uint32_t a;
    asm("{ .reg .u64 t; cvta.to.shared.u64 t, %1; cvt.u32.u64 %0, t; }"
        : "=r"(a) : "l"(p));
    return a;
}
__device__ __forceinline__ void cpa16(uint32_t dst, const void* src) {
    asm volatile("cp.async.cg.shared.global [%0], [%1], 16;"
                 :: "r"(dst), "l"(src));
}
#define CPA_COMMIT() asm volatile("cp.async.commit_group;")
#define CPA_WAIT0()  asm volatile("cp.async.wait_group 0;")

// ================= prep kernels =================
__global__ void pad_kernel(const float* __restrict__ lf) {
    size_t i = (size_t)blockIdx.x * blockDim.x + threadIdx.x;
    if (i < (size_t)NB * NC * SPAD) {
        int x = (int)(i % SPAD);
        size_t r = i / SPAD;
        g_ctxp[i] = (x < NS) ? lf[r * NS + x] : 0.f;
    }
}
__global__ void prep_ctxP(const float* __restrict__ lf) {
    size_t i = (size_t)blockIdx.x * blockDim.x + threadIdx.x;
    if (i >= (size_t)NB * ND2 * SPAD) return;
    int s = (int)(i % SPAD);
    size_t r = i / SPAD;
    int d2 = (int)(r % ND2);
    int b = (int)(r / ND2);
    float v0 = 0.f, v1 = 0.f;
    if (s < NS) {
        v0 = lf[((size_t)b * NC + 2 * d2) * NS + s];
        v1 = lf[((size_t)b * NC + 2 * d2 + 1) * NS + s];
    }
    uint32_t lo;
    g_ctxPH[i] = packbf(v0, v1, lo);
    g_ctxPL[i] = lo;
}
__global__ void prep_wP(const float* __restrict__ w) {
    size_t i = (size_t)blockIdx.x * blockDim.x + threadIdx.x;
    if (i >= (size_t)NB * ND2 * NT) return;
    int t = (int)(i % NT);
    size_t r = i / NT;
    int d2 = (int)(r % ND2);
    int c = (int)(r / ND2);
    float v0 = w[((size_t)c * NC + 2 * d2) * NT + t];
    float v1 = w[((size_t)c * NC + 2 * d2 + 1) * NT + t];
    uint32_t lo;
    g_wPH[i] = packbf(v0, v1, lo);
    g_wPL[i] = lo;
}
__global__ void prep_GP() {
    size_t i = (size_t)blockIdx.x * blockDim.x + threadIdx.x;
    if (i >= (size_t)NB * NS2 * SPAD) return;
    int s = (int)(i % SPAD);
    size_t r = i / SPAD;
    int k2 = (int)(r % NS2);
    int b = (int)(r / NS2);
    float v0 = g_G[((size_t)b * SPAD + 2 * k2) * SPAD + s];
    float v1 = g_G[((size_t)b * SPAD + 2 * k2 + 1) * SPAD + s];
    uint32_t lo;
    g_GPH[i] = packbf(v0, v1, lo);
    g_GPL[i] = lo;
}
__global__ void prep_aP() {
    size_t i = (size_t)blockIdx.x * blockDim.x + threadIdx.x;
    if (i >= (size_t)NPAIR * NS2 * NT) return;
    int t = (int)(i % NT);
    size_t r = i / NT;
    int s2 = (int)(r % NS2);
    int p = (int)(r / NS2);
    float v0 = g_a2u[((size_t)p * SPAD + 2 * s2) * NT + t];
    float v1 = g_a2u[((size_t)p * SPAD + 2 * s2 + 1) * NT + t];
    uint32_t lo;
    g_aPH[i] = packbf(v0, v1, lo);
    g_aPL[i] = lo;
}

// ================= gram (FFMA f32x2) =================
__device__ __forceinline__ ull pack2s(float x) {
    ull r; asm("mov.b64 %0, {%1, %1};" : "=l"(r) : "f"(x)); return r;
}
__device__ __forceinline__ void ffma2(ull& d, ull a, ull b) {
    asm("fma.rn.f32x2 %0, %1, %2, %0;" : "+l"(d) : "l"(a), "l"(b));
}
__device__ __forceinline__ void unpack2(float& lo, float& hi, ull v) {
    asm("mov.b64 {%0, %1}, %2;" : "=f"(lo), "=f"(hi) : "l"(v));
}
__device__ __forceinline__ void fma8x8p(ull (&acc)[8][4],
                                        const float4 a0, const float4 a1,
                                        const ulonglong2 b01, const ulonglong2 b23) {
    float av[8] = {a0.x, a0.y, a0.z, a0.w, a1.x, a1.y, a1.z, a1.w};
    ull bp[4] = {b01.x, b01.y, b23.x, b23.y};
#pragma unroll
    for (int i = 0; i < 8; ++i) {
        ull ap = pack2s(av[i]);
        ffma2(acc[i][0], ap, bp[0]);
        ffma2(acc[i][1], ap, bp[1]);
        ffma2(acc[i][2], ap, bp[2]);
        ffma2(acc[i][3], ap, bp[3]);
    }
}

__global__ __launch_bounds__(256) void gram_kernel() {
    const int byA[6] = {0, 0, 0, 1, 1, 2};
    const int bxA[6] = {0, 1, 2, 1, 2, 2};
    int p = blockIdx.x, b = blockIdx.y;
    int i0 = byA[p] * 128, j0 = bxA[p] * 128;
    __shared__ float At[32 * 128];
    __shared__ float Bt[32 * 128];
    const float* cp = g_ctxp + (size_t)b * NC * SPAD;
    int tid = threadIdx.x;
    int ti = tid & 15, si = tid >> 4;
    int il = si * 8, jl = ti * 8;
    ull acc[8][4] = {};
    for (int kc = 0; kc < 24; ++kc) {
        int k0 = kc * 32;
        __syncthreads();
        for (int i4 = tid; i4 < 1024; i4 += 256) {
            int kk = i4 >> 5, x4 = i4 & 31;
            const float* base = cp + (size_t)(k0 + kk) * SPAD;
            ((float4*)At)[i4] = *(const float4*)(base + i0 + x4 * 4);
            ((float4*)Bt)[i4] = *(const float4*)(base + j0 + x4 * 4);
        }
        __syncthreads();
#pragma unroll 4
        for (int k = 0; k < 32; ++k) {
            float4 a0 = *(const float4*)&At[k * 128 + il];
            float4 a1 = *(const float4*)&At[k * 128 + il + 4];
            ulonglong2 b01 = *(const ulonglong2*)&Bt[k * 128 + jl];
            ulonglong2 b23 = *(const ulonglong2*)&Bt[k * 128 + jl + 4];
            fma8x8p(acc, a0, a1, b01, b23);
        }
    }
    float c[8][8];
#pragma unroll
    for (int ii = 0; ii < 8; ++ii)
#pragma unroll
        for (int j = 0; j < 4; ++j)
            unpack2(c[ii][2 * j], c[ii][2 * j + 1], acc[ii][j]);
    float* Gb = g_G + (size_t)b * SPAD * SPAD;
#pragma unroll
    for (int ii = 0; ii < 8; ++ii) {
        int row = i0 + il + ii;
        *(float4*)&Gb[(size_t)row * SPAD + j0 + jl] =
            make_float4(c[ii][0], c[ii][1], c[ii][2], c[ii][3]);
        *(float4*)&Gb[(size_t)row * SPAD + j0 + jl + 4] =
            make_float4(c[ii][4], c[ii][5], c[ii][6], c[ii][7]);
    }
    if (i0 != j0) {
#pragma unroll
        for (int jj = 0; jj < 8; ++jj) {
            int row = j0 + jl + jj;
#pragma unroll
            for (int ii = 0; ii < 8; ++ii)
                Gb[(size_t)row * SPAD + i0 + il + ii] = c[ii][jj];
        }
    }
}

// ================= norms / gscore =================
__global__ void norms_kernel(const float* __restrict__ words,
                             const float* __restrict__ gfeat,
                             const float* __restrict__ sfeat) {
    int c = blockIdx.x;
    int tid = threadIdx.x;
    float s = 0.f;
    for (int d = 0; d < NC; ++d) {
        float v = words[((size_t)c * NC + d) * NT + tid];
        s = fmaf(v, v, s);
    }
    g_w1n[c * NT + tid] = sqrtf(s);
    float a = 0.f, bb = 0.f;
    for (int d = tid; d < NC; d += 64) {
        float v = gfeat[(size_t)c * NC + d];
        float w = sfeat[(size_t)c * NC + d];
        a = fmaf(v, v, a);
        bb = fmaf(w, w, bb);
    }
#pragma unroll
    for (int o = 16; o; o >>= 1) {
        a  += __shfl_xor_sync(0xffffffffu, a, o);
        bb += __shfl_xor_sync(0xffffffffu, bb, o);
    }
    __shared__ float r[4];
    int warp = tid >> 5, lane = tid & 31;
    if (lane == 0) { r[warp] = a; r[2 + warp] = bb; }
    __syncthreads();
    if (tid == 0) {
        g_gn[c] = sqrtf(r[0] + r[1]);
        g_sn[c] = sqrtf(r[2] + r[3]);
    }
}

__global__ void gscore_kernel(const float* __restrict__ gfeat,
                              const float* __restrict__ sfeat) {
    int i = blockIdx.x;
    int tid = threadIdx.x;
    int warp = tid >> 5, lane = tid & 31;
    for (int j = warp; j < NB; j += 8) {
        float acc = 0.f;
        for (int d = lane; d < NC; d += 32)
            acc = fmaf(gfeat[(size_t)i * NC + d], sfeat[(size_t)j * NC + d], acc);
#pragma unroll
        for (int o = 16; o; o >>= 1) acc += __shfl_xor_sync(0xffffffffu, acc, o);
        if (lane == 0) {
            float denom = fmaxf(g_gn[i] * g_sn[j], EPSV);
            g_sc0[i * NB + j] = TEMP3 * acc / denom;
        }
    }
}

// ================= Kernel A: bf16 mma scores + fused softmax =================
// smem u32 tiles: A [32 kpair][132], B [32 kpair][68]
#define A_CTH 0
#define A_CTL 16896
#define A_WTH 33792
#define A_WTL 42496
#define A_REDC 51200
#define A_REDW 53248
#define A_SMEM 55296

__global__ __launch_bounds__(256, 2) void scoreA_kernel(const int* __restrict__ caps) {
    extern __shared__ char smc[];
    uint32_t smb = smem_u32(smc);
    uint32_t* cth = (uint32_t*)(smc + A_CTH);
    uint32_t* ctl = (uint32_t*)(smc + A_CTL);
    uint32_t* wth = (uint32_t*)(smc + A_WTH);
    uint32_t* wtl = (uint32_t*)(smc + A_WTL);
    float* redc = (float*)(smc + A_REDC);
    float* redw = (float*)(smc + A_REDW);

    int tid = threadIdx.x, wid = tid >> 5, lane = tid & 31;
    int g = lane >> 2, tg = lane & 3;
    int p = blockIdx.x, b = p % NB, c = p / NB;
    const uint32_t* cH = g_ctxPH + (size_t)b * ND2 * SPAD;
    const uint32_t* cL = g_ctxPL + (size_t)b * ND2 * SPAD;
    const uint32_t* wHp = g_wPH + (size_t)c * ND2 * NT;
    const uint32_t* wLp = g_wPL + (size_t)c * ND2 * NT;
    int cap = caps[c];
    int capN = (cap + 7) >> 3;
    int bsegs = 2 * capN;     // 16B segments per B-tile row

    float colacc[16] = {}, w12acc[16] = {};
    float* au = g_a2u + (size_t)p * SPAD * NT;

    for (int st = 0; st < 3; ++st) {
        int s_base = st * 128;
        float acc[8][4] = {};
        for (int kc = 0; kc < 12; ++kc) {
            int k0 = kc * 32;   // kpair base
            __syncthreads();
            // A tiles (hi+lo): 2048 segs (32 rows x 32 segs x 2 planes)
            for (int i = tid; i < 2048; i += 256) {
                int h = i >> 10;
                int j = i & 1023;
                int kk = j >> 5, x4 = j & 31;
                const uint32_t* src = (h ? cL : cH) + (size_t)(k0 + kk) * SPAD + s_base + x4 * 4;
                cpa16(smb + (h ? A_CTL : A_CTH) + (uint32_t)(kk * 132 + x4 * 4) * 4, src);
            }
            // B tiles (hi+lo): 32 rows x bsegs x 2 planes
            int btot = 64 * bsegs;
            for (int i = tid; i < btot; i += 256) {
                int h = (i >= 32 * bsegs);
                int j = h ? i - 32 * bsegs : i;
                int kk = j / bsegs, x4 = j - kk * bsegs;
                const uint32_t* src = (h ? wLp : wHp) + (size_t)(k0 + kk) * NT + x4 * 4;
                cpa16(smb + (h ? A_WTL : A_WTH) + (uint32_t)(kk * 68 + x4 * 4) * 4, src);
            }
            CPA_COMMIT();
            CPA_WAIT0();
            __syncthreads();
            int arow = wid * 16 + g;
#pragma unroll
            for (int j = 0; j < 4; ++j) {
                int jb = j * 8;
                int r0 = (jb + tg) * 132 + arow;
                int r1 = (jb + tg + 4) * 132 + arow;
                uint32_t ah0 = cth[r0], ah1 = cth[r0 + 8];
                uint32_t ah2 = cth[r1], ah3 = cth[r1 + 8];
                uint32_t al0 = ctl[r0], al1 = ctl[r0 + 8];
                uint32_t al2 = ctl[r1], al3 = ctl[r1 + 8];
#pragma unroll
                for (int nt = 0; nt < 8; ++nt) {
                    if (nt < capN) {
                        int b0i = (jb + tg) * 68 + nt * 8 + g;
                        int b1i = (jb + tg + 4) * 68 + nt * 8 + g;
                        uint32_t bh0 = wth[b0i], bh1 = wth[b1i];
                        uint32_t bl0 = wtl[b0i], bl1 = wtl[b1i];
                        mma16(acc[nt], ah0, ah1, ah2, ah3, bh0, bh1);
                        mma16(acc[nt], ah0, ah1, ah2, ah3, bl0, bl1);
                        mma16(acc[nt], al0, al1, al2, al3, bh0, bh1);
                    }
                }
            }
        }
        // ---- fused masked softmax over t ----
        int s0 = s_base + wid * 16 + g;
        int s1 = s0 + 8;
        float mx0 = -1e30f, mx1 = -1e30f;
#pragma unroll
        for (int nt = 0; nt < 8; ++nt) {
            int col = nt * 8 + 2 * tg;
            if (col < cap)     { mx0 = fmaxf(mx0, acc[nt][0]); mx1 = fmaxf(mx1, acc[nt][2]); }
            if (col + 1 < cap) { mx0 = fmaxf(mx0, acc[nt][1]); mx1 = fmaxf(mx1, acc[nt][3]); }
        }
        mx0 = fmaxf(mx0, __shfl_xor_sync(0xffffffffu, mx0, 1));
        mx0 = fmaxf(mx0, __shfl_xor_sync(0xffffffffu, mx0, 2));
        mx1 = fmaxf(mx1, __shfl_xor_sync(0xffffffffu, mx1, 1));
        mx1 = fmaxf(mx1, __shfl_xor_sync(0xffffffffu, mx1, 2));
        float sm0 = 0.f, sm1 = 0.f;
#pragma unroll
        for (int nt = 0; nt < 8; ++nt) {
            int col = nt * 8 + 2 * tg;
            if (col < cap)     { sm0 += __expf(acc[nt][0] - mx0); sm1 += __expf(acc[nt][2] - mx1); }
            if (col + 1 < cap) { sm0 += __expf(acc[nt][1] - mx0); sm1 += __expf(acc[nt][3] - mx1); }
        }
        sm0 += __shfl_xor_sync(0xffffffffu, sm0, 1);
        sm0 += __shfl_xor_sync(0xffffffffu, sm0, 2);
        sm1 += __shfl_xor_sync(0xffffffffu, sm1, 1);
        sm1 += __shfl_xor_sync(0xffffffffu, sm1, 2);
        float inv0 = 1.f / sm0, inv1 = 1.f / sm1;
        bool v0ok = (s0 < NS), v1ok = (s1 < NS);
#pragma unroll
        for (int nt = 0; nt < 8; ++nt) {
            int col = nt * 8 + 2 * tg;
            float e00 = (col < cap)     ? __expf(acc[nt][0] - mx0) : 0.f;
            float e01 = (col + 1 < cap) ? __expf(acc[nt][1] - mx0) : 0.f;
            float e10 = (col < cap)     ? __expf(acc[nt][2] - mx1) : 0.f;
            float e11 = (col + 1 < cap) ? __expf(acc[nt][3] - mx1) : 0.f;
            float u00 = __expf(TEMP1 * (e00 * inv0));
            float u01 = __expf(TEMP1 * (e01 * inv0));
            float u10 = __expf(TEMP1 * (e10 * inv1));
            float u11 = __expf(TEMP1 * (e11 * inv1));
            float a00 = v0ok ? u00 : 0.f, a01 = v0ok ? u01 : 0.f;
            float a10 = v1ok ? u10 : 0.f, a11 = v1ok ? u11 : 0.f;
            colacc[nt * 2 + 0] += a00 + a10;
            colacc[nt * 2 + 1] += a01 + a11;
            w12acc[nt * 2 + 0] += (v0ok ? u00 * acc[nt][0] : 0.f) + (v1ok ? u10 * acc[nt][2] : 0.f);
            w12acc[nt * 2 + 1] += (v0ok ? u01 * acc[nt][1] : 0.f) + (v1ok ? u11 * acc[nt][3] : 0.f);
            *(float2*)&au[(size_t)s0 * NT + col] = make_float2(a00, a01);
            *(float2*)&au[(size_t)s1 * NT + col] = make_float2(a10, a11);
        }
    }
#pragma unroll
    for (int i = 0; i < 16; ++i) {
        float v = colacc[i], w = w12acc[i];
        v += __shfl_xor_sync(0xffffffffu, v, 4);
        v += __shfl_xor_sync(0xffffffffu, v, 8);
        v += __shfl_xor_sync(0xffffffffu, v, 16);
        w += __shfl_xor_sync(0xffffffffu, w, 4);
        w += __shfl_xor_sync(0xffffffffu, w, 8);
        w += __shfl_xor_sync(0xffffffffu, w, 16);
        colacc[i] = v; w12acc[i] = w;
    }
    __syncthreads();
    if (g == 0) {
#pragma unroll
        for (int i = 0; i < 16; ++i) {
            int col = (i >> 1) * 8 + 2 * tg + (i & 1);
            redc[wid * 64 + col] = colacc[i];
            redw[wid * 64 + col] = w12acc[i];
        }
    }
    __syncthreads();
    if (tid < 64) {
        float cs = 0.f, ws = 0.f;
#pragma unroll
        for (int w = 0; w < 8; ++w) { cs += redc[w * 64 + tid]; ws += redw[w * 64 + tid]; }
        g_cols[p * 64 + tid] = cs;
        g_w12[p * 64 + tid] = ws;
    }
}

// ================= Kernel B: bf16 mma Gram quadratic form =================
#define B_CTH 0
#define B_CTL 16896
#define B_ATH 33792
#define B_ATL 42496
#define B_W2R 51200
#define B_SMEM 53248

__global__ __launch_bounds__(256, 2) void w2B_kernel(const int* __restrict__ caps) {
    extern __shared__ char smc[];
    uint32_t smb = smem_u32(smc);
    uint32_t* cth = (uint32_t*)(smc + B_CTH);
    uint32_t* ctl = (uint32_t*)(smc + B_CTL);
    uint32_t* ath = (uint32_t*)(smc + B_ATH);
    uint32_t* atl = (uint32_t*)(smc + B_ATL);
    float* w2red = (float*)(smc + B_W2R);

    int tid = threadIdx.x, wid = tid >> 5, lane = tid & 31;
    int g = lane >> 2, tg = lane & 3;
    int p = blockIdx.x, b = p % NB, c = p / NB;
    const uint32_t* GHp = g_GPH + (size_t)b * NS2 * SPAD;
    const uint32_t* GLp = g_GPL + (size_t)b * NS2 * SPAD;
    const uint32_t* aHp = g_aPH + (size_t)p * NS2 * NT;
    const uint32_t* aLp = g_aPL + (size_t)p * NS2 * NT;
    const float* au = g_a2u + (size_t)p * SPAD * NT;
    int cap = caps[c];
    int capN = (cap + 7) >> 3;
    int bsegs = 2 * capN;

    float w2acc[16] = {};

    for (int st = 0; st < 3; ++st) {
        int s_base = st * 128;
        float acc[8][4] = {};
        for (int kc = 0; kc < 6; ++kc) {
            int k0 = kc * 32;   // kpair base (0..191)
            __syncthreads();
            for (int i = tid; i < 2048; i += 256) {
                int h = i >> 10;
                int j = i & 1023;
                int kk = j >> 5, x4 = j & 31;
                const uint32_t* src = (h ? GLp : GHp) + (size_t)(k0 + kk) * SPAD + s_base + x4 * 4;
                cpa16(smb + (h ? B_CTL : B_CTH) + (uint32_t)(kk * 132 + x4 * 4) * 4, src);
            }
            int btot = 64 * bsegs;
            for (int i = tid; i < btot; i += 256) {
                int h = (i >= 32 * bsegs);
                int j = h ? i - 32 * bsegs : i;
                int kk = j / bsegs, x4 = j - kk * bsegs;
                const uint32_t* src = (h ? aLp : aHp) + (size_t)(k0 + kk) * NT + x4 * 4;
                cpa16(smb + (h ? B_ATL : B_ATH) + (uint32_t)(kk * 68 + x4 * 4) * 4, src);
            }
            CPA_COMMIT();
            CPA_WAIT0();
            __syncthreads();
            int arow = wid * 16 + g;
#pragma unroll
            for (int j = 0; j < 4; ++j) {
                int jb = j * 8;
                int r0 = (jb + tg) * 132 + arow;
                int r1 = (jb + tg + 4) * 132 + arow;
                uint32_t ah0 = cth[r0], ah1 = cth[r0 + 8];
                uint32_t ah2 = cth[r1], ah3 = cth[r1 + 8];
                uint32_t al0 = ctl[r0], al1 = ctl[r0 + 8];
                uint32_t al2 = ctl[r1], al3 = ctl[r1 + 8];
#pragma unroll
                for (int nt = 0; nt < 8; ++nt) {
                    if (nt < capN) {
                        int b0i = (jb + tg) * 68 + nt * 8 + g;
                        int b1i = (jb + tg + 4) * 68 + nt * 8 + g;
                        uint32_t bh0 = ath[b0i], bh1 = ath[b1i];
                        uint32_t bl0 = atl[b0i], bl1 = atl[b1i];
                        mma16(acc[nt], ah0, ah1, ah2, ah3, bh0, bh1);
                        mma16(acc[nt], ah0, ah1, ah2, ah3, bl0, bl1);
                        mma16(acc[nt], al0, al1, al2, al3, bh0, bh1);
                    }
                }
            }
        }
        // contraction: w2[t] += a2u[s,t] * Y[s,t]
        int s0 = s_base + wid * 16 + g;
        int s1 = s0 + 8;
#pragma unroll
        for (int nt = 0; nt < 8; ++nt) {
            int col = nt * 8 + 2 * tg;
            float2 a0v = *(const float2*)&au[(size_t)s0 * NT + col];
            float2 a1v = *(const float2*)&au[(size_t)s1 * NT + col];
            w2acc[nt * 2 + 0] += a0v.x * acc[nt][0] + a1v.x * acc[nt][2];
            w2acc[nt * 2 + 1] += a0v.y * acc[nt][1] + a1v.y * acc[nt][3];
        }
    }
#pragma unroll
    for (int i = 0; i < 16; ++i) {
        float v = w2acc[i];
        v += __shfl_xor_sync(0xffffffffu, v, 4);
        v += __shfl_xor_sync(0xffffffffu, v, 8);
        v += __shfl_xor_sync(0xffffffffu, v, 16);
        w2acc[i] = v;
    }
    __syncthreads();
    if (g == 0) {
#pragma unroll
        for (int i = 0; i < 16; ++i) {
            int col = (i >> 1) * 8 + 2 * tg + (i & 1);
            w2red[wid * 64 + col] = w2acc[i];
        }
    }
    __syncthreads();
    if (tid < 64) {
        float s = 0.f;
#pragma unroll
        for (int w = 0; w < 8; ++w) s += w2red[w * 64 + tid];
        g_w2[p * 64 + tid] = s;
    }
}

// ================= finalizers =================
__global__ void csim_kernel(const int* __restrict__ caps) {
    int p = blockIdx.x, b = p % NB, c = p / NB;
    int t = threadIdx.x;
    float cs = g_cols[p * 64 + t];
    float ci = 1.f / cs;
    float w12 = g_w12[p * 64 + t] * ci;
    float w2 = ci * sqrtf(fmaxf(g_w2[p * 64 + t], 0.f));
    float w1 = g_w1n[c * 64 + t];
    float sim = w12 / fmaxf(w1 * w2, EPSV);
    float row = (t < caps[c]) ? __expf(TEMP2 * sim) : 0.f;
#pragma unroll
    for (int o = 16; o; o >>= 1) row += __shfl_xor_sync(0xffffffffu, row, o);
    __shared__ float sred[2];
    if ((t & 31) == 0) sred[t >> 5] = row;
    __syncthreads();
    if (t == 0) g_sims[b * NB + c] = TEMP3 * logf(sred[0] + sred[1]);
}

__global__ void att_kernel(float* __restrict__ ao) {
    int b = blockIdx.x;
    int p = b * NB + b;
    int tid = threadIdx.x;
    __shared__ float ci[64];
    if (tid < 64) ci[tid] = 1.f / g_cols[p * 64 + tid];
    __syncthreads();
    const float* au = g_a2u + (size_t)p * SPAD * NT;
    for (int i = tid; i < NS * NT; i += 256) {
        int s = i >> 6, t = i & 63;
        ao[((size_t)b * NT + t) * NS + s] = au[(size_t)s * NT + t] * ci[t];
    }
}

__global__ void loss_kernel(float* __restrict__ out) {
    __shared__ float part[4][NB];
    int i = threadIdx.x;
    if (i < NB) {
        const float* Ms = g_sims;
        const float* Mg = g_sc0;
        float m, sum;
        m = -INFINITY;
        for (int j = 0; j < NB; ++j) m = fmaxf(m, Ms[i * NB + j]);
        sum = 0.f;
        for (int j = 0; j < NB; ++j) sum += expf(Ms[i * NB + j] - m);
        part[0][i] = m + logf(sum) - Ms[i * NB + i];
        m = -INFINITY;
        for (int j = 0; j < NB; ++j) m = fmaxf(m, Ms[j * NB + i]);
        sum = 0.f;
        for (int j = 0; j < NB; ++j) sum += expf(Ms[j * NB + i] - m);
        part[1][i] = m + logf(sum) - Ms[i * NB + i];
        m = -INFINITY;
        for (int j = 0; j < NB; ++j) m = fmaxf(m, Mg[i * NB + j]);
        sum = 0.f;
        for (int j = 0; j < NB; ++j) sum += expf(Mg[i * NB + j] - m);
        part[2][i] = m + logf(sum) - Mg[i * NB + i];
        m = -INFINITY;
        for (int j = 0; j < NB; ++j) m = fmaxf(m, Mg[j * NB + i]);
        sum = 0.f;
        for (int j = 0; j < NB; ++j) sum += expf(Mg[j * NB + i] - m);
        part[3][i] = m + logf(sum) - Mg[i * NB + i];
    }
    __syncthreads();
    if (i == 0) {
        float l = 0.f;
        for (int k = 0; k < 4; ++k) {
            float s = 0.f;
            for (int j = 0; j < NB; ++j) s += part[k][j];
            l += s * (1.f / (float)NB);
        }
        out[0] = l;
    }
}

// ================= launch =================
extern "C" void kernel_launch(void* const* d_in, const int* in_sizes, int n_in,
                              void* d_out, int out_size) {
    const float* gfeat  = (const float*)d_in[0];
    const float* localf = (const float*)d_in[1];
    const float* words  = (const float*)d_in[2];
    const float* sfeat  = (const float*)d_in[3];
    const int*   caps   = (const int*)d_in[4];
    float* out = (float*)d_out;

    cudaFuncSetAttribute(scoreA_kernel, cudaFuncAttributeMaxDynamicSharedMemorySize, A_SMEM);
    cudaFuncSetAttribute(w2B_kernel, cudaFuncAttributeMaxDynamicSharedMemorySize, B_SMEM);

    size_t n_pad = (size_t)NB * NC * SPAD;
    pad_kernel<<<(unsigned)((n_pad + 255) / 256), 256>>>(localf);
    gram_kernel<<<dim3(6, NB), 256>>>();
    prep_GP<<<(unsigned)(((size_t)NB * NS2 * SPAD + 255) / 256), 256>>>();
    prep_ctxP<<<(unsigned)(((size_t)NB * ND2 * SPAD + 255) / 256), 256>>>(localf);
    prep_wP<<<(unsigned)(((size_t)NB * ND2 * NT + 255) / 256), 256>>>(words);

    norms_kernel<<<NB, 64>>>(words, gfeat, sfeat);
    gscore_kernel<<<NB, 256>>>(gfeat, sfeat);

    scoreA_kernel<<<NPAIR, 256, A_SMEM>>>(caps);
    prep_aP<<<(unsigned)(((size_t)NPAIR * NS2 * NT + 255) / 256), 256>>>();
    w2B_kernel<<<NPAIR, 256, B_SMEM>>>(caps);
    csim_kernel<<<NPAIR, 64>>>(caps);

    int wa = (out_size >= 1 + NB * NT * NS) ? 1 : 0;
    if (wa) att_kernel<<<NB, 256>>>(out + 1);
    loss_kernel<<<1, 64>>>(out);
}

// round 14
// speedup vs baseline: 2.1775x; 1.0232x over previous
#include <cuda_runtime.h>
#include <cuda_bf16.h>
#include <math.h>
#include <stdint.h>

#define NB 48
#define NC 768
#define NS 361
#define NT 64
#define SPAD 384
#define ND2 (NC / 2)
#define NS2 (SPAD / 2)
#define NPAIR (NB * NB)

#define TEMP1 4.0f
#define TEMP2 5.0f
#define TEMP3 10.0f
#define EPSV  1e-8f

typedef unsigned long long ull;

// ================= device scratch =================
__device__ float g_ctxp[(size_t)NB * NC * SPAD];
__device__ float g_G[(size_t)NB * SPAD * SPAD];
__device__ uint32_t g_ctxPH[(size_t)NB * ND2 * SPAD];
__device__ uint32_t g_ctxPL[(size_t)NB * ND2 * SPAD];
__device__ uint32_t g_wPH[(size_t)NB * ND2 * NT];
__device__ uint32_t g_wPL[(size_t)NB * ND2 * NT];
__device__ uint32_t g_GPH[(size_t)NB * NS2 * SPAD];
__device__ uint32_t g_GPL[(size_t)NB * NS2 * SPAD];
__device__ float g_a2u[(size_t)NPAIR * SPAD * NT];
__device__ uint32_t g_aPH[(size_t)NPAIR * NS2 * NT];
__device__ uint32_t g_aPL[(size_t)NPAIR * NS2 * NT];
__device__ float g_cols[NPAIR * NT];
__device__ float g_w12[NPAIR * NT];
__device__ float g_w2[NPAIR * NT];
__device__ float g_w1n[NB * NT];
__device__ float g_gn[NB];
__device__ float g_sn[NB];
__device__ float g_sc0[NB * NB];
__device__ float g_sims[NB * NB];

// ================= helpers =================
__device__ __forceinline__ uint32_t packbf(float v0, float v1, uint32_t& lo) {
    __nv_bfloat16 h0 = __float2bfloat16(v0);
    __nv_bfloat16 h1 = __float2bfloat16(v1);
    __nv_bfloat16 l0 = __float2bfloat16(v0 - __bfloat162float(h0));
    __nv_bfloat16 l1 = __float2bfloat16(v1 - __bfloat162float(h1));
    lo = (uint32_t)__bfloat16_as_ushort(l0) | ((uint32_t)__bfloat16_as_ushort(l1) << 16);
    return (uint32_t)__bfloat16_as_ushort(h0) | ((uint32_t)__bfloat16_as_ushort(h1) << 16);
}
__device__ __forceinline__ void mma16(float* c, uint32_t a0, uint32_t a1,
                                      uint32_t a2, uint32_t a3,
                                      uint32_t b0, uint32_t b1) {
    asm volatile(
        "mma.sync.aligned.m16n8k16.row.col.f32.bf16.bf16.f32 "
        "{%0,%1,%2,%3}, {%4,%5,%6,%7}, {%8,%9}, {%0,%1,%2,%3};"
        : "+f"(c[0]), "+f"(c[1]), "+f"(c[2]), "+f"(c[3])
        : "r"(a0), "r"(a1), "r"(a2), "r"(a3), "r"(b0), "r"(b1));
}
__device__ __forceinline__ uint32_t smem_u32(const void* p) {
    uint32_t a;
    asm("{ .reg .u64 t; cvta.to.shared.u64 t, %1; cvt.u32.u64 %0, t; }"
        : "=r"(a) : "l"(p));
    return a;
}
__device__ __forceinline__ void cpa16(uint32_t dst, const void* src) {
    asm volatile("cp.async.cg.shared.global [%0], [%1], 16;"
                 :: "r"(dst), "l"(src));
}
#define CPA_COMMIT() asm volatile("cp.async.commit_group;")
#define CPA_WAIT0()  asm volatile("cp.async.wait_group 0;")
#define CPA_WAIT1()  asm volatile("cp.async.wait_group 1;")

// stage layout (bytes within one 51200-B stage)
#define ST_CTH 0
#define ST_CTL 16896
#define ST_WTH 33792
#define ST_WTL 42496
#define ST_SIZE 51200u

// Shared stage loader: A tiles [32 kpair][128 cols] (stride 132 u32),
// B tiles [32 kpair][bsegs*4 cols] (stride 68 u32), hi+lo planes.
__device__ __forceinline__ void load_stage(uint32_t dstbase,
    const uint32_t* aH, const uint32_t* aL,
    const uint32_t* bH, const uint32_t* bL,
    int k0, int s_base, int bsegs, int tid) {
    for (int i = tid; i < 2048; i += 256) {
        int h = i >> 10;
        int j = i & 1023;
        int kk = j >> 5, x4 = j & 31;
        const uint32_t* src = (h ? aL : aH) + (size_t)(k0 + kk) * SPAD + s_base + x4 * 4;
        cpa16(dstbase + (h ? ST_CTL : ST_CTH) + (uint32_t)(kk * 132 + x4 * 4) * 4, src);
    }
    int btot = 64 * bsegs;
    for (int i = tid; i < btot; i += 256) {
        int h = (i >= 32 * bsegs);
        int j = h ? i - 32 * bsegs : i;
        int kk = j / bsegs, x4 = j - kk * bsegs;
        const uint32_t* src = (h ? bL : bH) + (size_t)(k0 + kk) * NT + x4 * 4;
        cpa16(dstbase + (h ? ST_WTL : ST_WTH) + (uint32_t)(kk * 68 + x4 * 4) * 4, src);
    }
    CPA_COMMIT();
}

// ================= prep kernels =================
__global__ void pad_kernel(const float* __restrict__ lf) {
    size_t i = (size_t)blockIdx.x * blockDim.x + threadIdx.x;
    if (i < (size_t)NB * NC * SPAD) {
        int x = (int)(i % SPAD);
        size_t r = i / SPAD;
        g_ctxp[i] = (x < NS) ? lf[r * NS + x] : 0.f;
    }
}
__global__ void prep_ctxP(const float* __restrict__ lf) {
    size_t i = (size_t)blockIdx.x * blockDim.x + threadIdx.x;
    if (i >= (size_t)NB * ND2 * SPAD) return;
    int s = (int)(i % SPAD);
    size_t r = i / SPAD;
    int d2 = (int)(r % ND2);
    int b = (int)(r / ND2);
    float v0 = 0.f, v1 = 0.f;
    if (s < NS) {
        v0 = lf[((size_t)b * NC + 2 * d2) * NS + s];
        v1 = lf[((size_t)b * NC + 2 * d2 + 1) * NS + s];
    }
    uint32_t lo;
    g_ctxPH[i] = packbf(v0, v1, lo);
    g_ctxPL[i] = lo;
}
__global__ void prep_wP(const float* __restrict__ w) {
    size_t i = (size_t)blockIdx.x * blockDim.x + threadIdx.x;
    if (i >= (size_t)NB * ND2 * NT) return;
    int t = (int)(i % NT);
    size_t r = i / NT;
    int d2 = (int)(r % ND2);
    int c = (int)(r / ND2);
    float v0 = w[((size_t)c * NC + 2 * d2) * NT + t];
    float v1 = w[((size_t)c * NC + 2 * d2 + 1) * NT + t];
    uint32_t lo;
    g_wPH[i] = packbf(v0, v1, lo);
    g_wPL[i] = lo;
}
__global__ void prep_GP() {
    size_t i = (size_t)blockIdx.x * blockDim.x + threadIdx.x;
    if (i >= (size_t)NB * NS2 * SPAD) return;
    int s = (int)(i % SPAD);
    size_t r = i / SPAD;
    int k2 = (int)(r % NS2);
    int b = (int)(r / NS2);
    float v0 = g_G[((size_t)b * SPAD + 2 * k2) * SPAD + s];
    float v1 = g_G[((size_t)b * SPAD + 2 * k2 + 1) * SPAD + s];
    uint32_t lo;
    g_GPH[i] = packbf(v0, v1, lo);
    g_GPL[i] = lo;
}
__global__ void prep_aP() {
    size_t i = (size_t)blockIdx.x * blockDim.x + threadIdx.x;
    if (i >= (size_t)NPAIR * NS2 * NT) return;
    int t = (int)(i % NT);
    size_t r = i / NT;
    int s2 = (int)(r % NS2);
    int p = (int)(r / NS2);
    float v0 = g_a2u[((size_t)p * SPAD + 2 * s2) * NT + t];
    float v1 = g_a2u[((size_t)p * SPAD + 2 * s2 + 1) * NT + t];
    uint32_t lo;
    g_aPH[i] = packbf(v0, v1, lo);
    g_aPL[i] = lo;
}

// ================= gram (FFMA f32x2) =================
__device__ __forceinline__ ull pack2s(float x) {
    ull r; asm("mov.b64 %0, {%1, %1};" : "=l"(r) : "f"(x)); return r;
}
__device__ __forceinline__ void ffma2(ull& d, ull a, ull b) {
    asm("fma.rn.f32x2 %0, %1, %2, %0;" : "+l"(d) : "l"(a), "l"(b));
}
__device__ __forceinline__ void unpack2(float& lo, float& hi, ull v) {
    asm("mov.b64 {%0, %1}, %2;" : "=f"(lo), "=f"(hi) : "l"(v));
}
__device__ __forceinline__ void fma8x8p(ull (&acc)[8][4],
                                        const float4 a0, const float4 a1,
                                        const ulonglong2 b01, const ulonglong2 b23) {
    float av[8] = {a0.x, a0.y, a0.z, a0.w, a1.x, a1.y, a1.z, a1.w};
    ull bp[4] = {b01.x, b01.y, b23.x, b23.y};
#pragma unroll
    for (int i = 0; i < 8; ++i) {
        ull ap = pack2s(av[i]);
        ffma2(acc[i][0], ap, bp[0]);
        ffma2(acc[i][1], ap, bp[1]);
        ffma2(acc[i][2], ap, bp[2]);
        ffma2(acc[i][3], ap, bp[3]);
    }
}

__global__ __launch_bounds__(256) void gram_kernel() {
    const int byA[6] = {0, 0, 0, 1, 1, 2};
    const int bxA[6] = {0, 1, 2, 1, 2, 2};
    int p = blockIdx.x, b = blockIdx.y;
    int i0 = byA[p] * 128, j0 = bxA[p] * 128;
    __shared__ float At[32 * 128];
    __shared__ float Bt[32 * 128];
    const float* cp = g_ctxp + (size_t)b * NC * SPAD;
    int tid = threadIdx.x;
    int ti = tid & 15, si = tid >> 4;
    int il = si * 8, jl = ti * 8;
    ull acc[8][4] = {};
    for (int kc = 0; kc < 24; ++kc) {
        int k0 = kc * 32;
        __syncthreads();
        for (int i4 = tid; i4 < 1024; i4 += 256) {
            int kk = i4 >> 5, x4 = i4 & 31;
            const float* base = cp + (size_t)(k0 + kk) * SPAD;
            ((float4*)At)[i4] = *(const float4*)(base + i0 + x4 * 4);
            ((float4*)Bt)[i4] = *(const float4*)(base + j0 + x4 * 4);
        }
        __syncthreads();
#pragma unroll 4
        for (int k = 0; k < 32; ++k) {
            float4 a0 = *(const float4*)&At[k * 128 + il];
            float4 a1 = *(const float4*)&At[k * 128 + il + 4];
            ulonglong2 b01 = *(const ulonglong2*)&Bt[k * 128 + jl];
            ulonglong2 b23 = *(const ulonglong2*)&Bt[k * 128 + jl + 4];
            fma8x8p(acc, a0, a1, b01, b23);
        }
    }
    float c[8][8];
#pragma unroll
    for (int ii = 0; ii < 8; ++ii)
#pragma unroll
        for (int j = 0; j < 4; ++j)
            unpack2(c[ii][2 * j], c[ii][2 * j + 1], acc[ii][j]);
    float* Gb = g_G + (size_t)b * SPAD * SPAD;
#pragma unroll
    for (int ii = 0; ii < 8; ++ii) {
        int row = i0 + il + ii;
        *(float4*)&Gb[(size_t)row * SPAD + j0 + jl] =
            make_float4(c[ii][0], c[ii][1], c[ii][2], c[ii][3]);
        *(float4*)&Gb[(size_t)row * SPAD + j0 + jl + 4] =
            make_float4(c[ii][4], c[ii][5], c[ii][6], c[ii][7]);
    }
    if (i0 != j0) {
#pragma unroll
        for (int jj = 0; jj < 8; ++jj) {
            int row = j0 + jl + jj;
#pragma unroll
            for (int ii = 0; ii < 8; ++ii)
                Gb[(size_t)row * SPAD + i0 + il + ii] = c[ii][jj];
        }
    }
}

// ================= norms / gscore =================
__global__ void norms_kernel(const float* __restrict__ words,
                             const float* __restrict__ gfeat,
                             const float* __restrict__ sfeat) {
    int c = blockIdx.x;
    int tid = threadIdx.x;
    float s = 0.f;
    for (int d = 0; d < NC; ++d) {
        float v = words[((size_t)c * NC + d) * NT + tid];
        s = fmaf(v, v, s);
    }
    g_w1n[c * NT + tid] = sqrtf(s);
    float a = 0.f, bb = 0.f;
    for (int d = tid; d < NC; d += 64) {
        float v = gfeat[(size_t)c * NC + d];
        float w = sfeat[(size_t)c * NC + d];
        a = fmaf(v, v, a);
        bb = fmaf(w, w, bb);
    }
#pragma unroll
    for (int o = 16; o; o >>= 1) {
        a  += __shfl_xor_sync(0xffffffffu, a, o);
        bb += __shfl_xor_sync(0xffffffffu, bb, o);
    }
    __shared__ float r[4];
    int warp = tid >> 5, lane = tid & 31;
    if (lane == 0) { r[warp] = a; r[2 + warp] = bb; }
    __syncthreads();
    if (tid == 0) {
        g_gn[c] = sqrtf(r[0] + r[1]);
        g_sn[c] = sqrtf(r[2] + r[3]);
    }
}

__global__ void gscore_kernel(const float* __restrict__ gfeat,
                              const float* __restrict__ sfeat) {
    int i = blockIdx.x;
    int tid = threadIdx.x;
    int warp = tid >> 5, lane = tid & 31;
    for (int j = warp; j < NB; j += 8) {
        float acc = 0.f;
        for (int d = lane; d < NC; d += 32)
            acc = fmaf(gfeat[(size_t)i * NC + d], sfeat[(size_t)j * NC + d], acc);
#pragma unroll
        for (int o = 16; o; o >>= 1) acc += __shfl_xor_sync(0xffffffffu, acc, o);
        if (lane == 0) {
            float denom = fmaxf(g_gn[i] * g_sn[j], EPSV);
            g_sc0[i * NB + j] = TEMP3 * acc / denom;
        }
    }
}

// ================= Kernel A: bf16 mma, double-buffered =================
#define A_REDC 102400
#define A_REDW 104448
#define A_SMEM 106496

__global__ __launch_bounds__(256, 2) void scoreA_kernel(const int* __restrict__ caps) {
    extern __shared__ char smc[];
    uint32_t smb = smem_u32(smc);
    float* redc = (float*)(smc + A_REDC);
    float* redw = (float*)(smc + A_REDW);

    int tid = threadIdx.x, wid = tid >> 5, lane = tid & 31;
    int g = lane >> 2, tg = lane & 3;
    int p = blockIdx.x, b = p % NB, c = p / NB;
    const uint32_t* cH = g_ctxPH + (size_t)b * ND2 * SPAD;
    const uint32_t* cL = g_ctxPL + (size_t)b * ND2 * SPAD;
    const uint32_t* wHp = g_wPH + (size_t)c * ND2 * NT;
    const uint32_t* wLp = g_wPL + (size_t)c * ND2 * NT;
    int cap = caps[c];
    int capN = (cap + 7) >> 3;
    int bsegs = 2 * capN;

    float colacc[16] = {}, w12acc[16] = {};
    float* au = g_a2u + (size_t)p * SPAD * NT;

    int pb = 0;
    // preload (st=0, kc=0)
    load_stage(smb, cH, cL, wHp, wLp, 0, 0, bsegs, tid);

    for (int st = 0; st < 3; ++st) {
        int s_base = st * 128;
        float acc[8][4] = {};
        for (int kc = 0; kc < 12; ++kc) {
            int gi = st * 12 + kc;
            if (gi < 35) {
                int nst = (kc < 11) ? st : st + 1;
                int nkc = (kc < 11) ? kc + 1 : 0;
                load_stage(smb + (uint32_t)(pb ^ 1) * ST_SIZE,
                           cH, cL, wHp, wLp, nkc * 32, nst * 128, bsegs, tid);
                CPA_WAIT1();
            } else {
                CPA_WAIT0();
            }
            __syncthreads();
            uint32_t* base = (uint32_t*)(smc + (uint32_t)pb * ST_SIZE);
            uint32_t* cth = base;
            uint32_t* ctl = base + 4224;
            uint32_t* wth = base + 8448;
            uint32_t* wtl = base + 10624;
            int arow = wid * 16 + g;
#pragma unroll
            for (int j = 0; j < 4; ++j) {
                int jb = j * 8;
                int r0 = (jb + tg) * 132 + arow;
                int r1 = (jb + tg + 4) * 132 + arow;
                uint32_t ah0 = cth[r0], ah1 = cth[r0 + 8];
                uint32_t ah2 = cth[r1], ah3 = cth[r1 + 8];
                uint32_t al0 = ctl[r0], al1 = ctl[r0 + 8];
                uint32_t al2 = ctl[r1], al3 = ctl[r1 + 8];
#pragma unroll
                for (int nt = 0; nt < 8; ++nt) {
                    if (nt < capN) {
                        int b0i = (jb + tg) * 68 + nt * 8 + g;
                        int b1i = (jb + tg + 4) * 68 + nt * 8 + g;
                        uint32_t bh0 = wth[b0i], bh1 = wth[b1i];
                        uint32_t bl0 = wtl[b0i], bl1 = wtl[b1i];
                        mma16(acc[nt], ah0, ah1, ah2, ah3, bh0, bh1);
                        mma16(acc[nt], ah0, ah1, ah2, ah3, bl0, bl1);
                        mma16(acc[nt], al0, al1, al2, al3, bh0, bh1);
                    }
                }
            }
            __syncthreads();
            pb ^= 1;
        }
        // ---- fused masked softmax over t (next stripe's tile loads in flight) ----
        int s0 = s_base + wid * 16 + g;
        int s1 = s0 + 8;
        float mx0 = -1e30f, mx1 = -1e30f;
#pragma unroll
        for (int nt = 0; nt < 8; ++nt) {
            int col = nt * 8 + 2 * tg;
            if (col < cap)     { mx0 = fmaxf(mx0, acc[nt][0]); mx1 = fmaxf(mx1, acc[nt][2]); }
            if (col + 1 < cap) { mx0 = fmaxf(mx0, acc[nt][1]); mx1 = fmaxf(mx1, acc[nt][3]); }
        }
        mx0 = fmaxf(mx0, __shfl_xor_sync(0xffffffffu, mx0, 1));
        mx0 = fmaxf(mx0, __shfl_xor_sync(0xffffffffu, mx0, 2));
        mx1 = fmaxf(mx1, __shfl_xor_sync(0xffffffffu, mx1, 1));
        mx1 = fmaxf(mx1, __shfl_xor_sync(0xffffffffu, mx1, 2));
        float sm0 = 0.f, sm1 = 0.f;
#pragma unroll
        for (int nt = 0; nt < 8; ++nt) {
            int col = nt * 8 + 2 * tg;
            if (col < cap)     { sm0 += __expf(acc[nt][0] - mx0); sm1 += __expf(acc[nt][2] - mx1); }
            if (col + 1 < cap) { sm0 += __expf(acc[nt][1] - mx0); sm1 += __expf(acc[nt][3] - mx1); }
        }
        sm0 += __shfl_xor_sync(0xffffffffu, sm0, 1);
        sm0 += __shfl_xor_sync(0xffffffffu, sm0, 2);
        sm1 += __shfl_xor_sync(0xffffffffu, sm1, 1);
        sm1 += __shfl_xor_sync(0xffffffffu, sm1, 2);
        float inv0 = 1.f / sm0, inv1 = 1.f / sm1;
        bool v0ok = (s0 < NS), v1ok = (s1 < NS);
#pragma unroll
        for (int nt = 0; nt < 8; ++nt) {
            int col = nt * 8 + 2 * tg;
            float e00 = (col < cap)     ? __expf(acc[nt][0] - mx0) : 0.f;
            float e01 = (col + 1 < cap) ? __expf(acc[nt][1] - mx0) : 0.f;
            float e10 = (col < cap)     ? __expf(acc[nt][2] - mx1) : 0.f;
            float e11 = (col + 1 < cap) ? __expf(acc[nt][3] - mx1) : 0.f;
            float u00 = __expf(TEMP1 * (e00 * inv0));
            float u01 = __expf(TEMP1 * (e01 * inv0));
            float u10 = __expf(TEMP1 * (e10 * inv1));
            float u11 = __expf(TEMP1 * (e11 * inv1));
            float a00 = v0ok ? u00 : 0.f, a01 = v0ok ? u01 : 0.f;
            float a10 = v1ok ? u10 : 0.f, a11 = v1ok ? u11 : 0.f;
            colacc[nt * 2 + 0] += a00 + a10;
            colacc[nt * 2 + 1] += a01 + a11;
            w12acc[nt * 2 + 0] += (v0ok ? u00 * acc[nt][0] : 0.f) + (v1ok ? u10 * acc[nt][2] : 0.f);
            w12acc[nt * 2 + 1] += (v0ok ? u01 * acc[nt][1] : 0.f) + (v1ok ? u11 * acc[nt][3] : 0.f);
            *(float2*)&au[(size_t)s0 * NT + col] = make_float2(a00, a01);
            *(float2*)&au[(size_t)s1 * NT + col] = make_float2(a10, a11);
        }
    }
#pragma unroll
    for (int i = 0; i < 16; ++i) {
        float v = colacc[i], w = w12acc[i];
        v += __shfl_xor_sync(0xffffffffu, v, 4);
        v += __shfl_xor_sync(0xffffffffu, v, 8);
        v += __shfl_xor_sync(0xffffffffu, v, 16);
        w += __shfl_xor_sync(0xffffffffu, w, 4);
        w += __shfl_xor_sync(0xffffffffu, w, 8);
        w += __shfl_xor_sync(0xffffffffu, w, 16);
        colacc[i] = v; w12acc[i] = w;
    }
    __syncthreads();
    if (g == 0) {
#pragma unroll
        for (int i = 0; i < 16; ++i) {
            int col = (i >> 1) * 8 + 2 * tg + (i & 1);
            redc[wid * 64 + col] = colacc[i];
            redw[wid * 64 + col] = w12acc[i];
        }
    }
    __syncthreads();
    if (tid < 64) {
        float cs = 0.f, ws = 0.f;
#pragma unroll
        for (int w = 0; w < 8; ++w) { cs += redc[w * 64 + tid]; ws += redw[w * 64 + tid]; }
        g_cols[p * 64 + tid] = cs;
        g_w12[p * 64 + tid] = ws;
    }
}

// ================= Kernel B: bf16 mma Gram quadratic form, double-buffered ======
#define B_W2R 102400
#define B_SMEM 104448

__global__ __launch_bounds__(256, 2) void w2B_kernel(const int* __restrict__ caps) {
    extern __shared__ char smc[];
    uint32_t smb = smem_u32(smc);
    float* w2red = (float*)(smc + B_W2R);

    int tid = threadIdx.x, wid = tid >> 5, lane = tid & 31;
    int g = lane >> 2, tg = lane & 3;
    int p = blockIdx.x, b = p % NB, c = p / NB;
    const uint32_t* GHp = g_GPH + (size_t)b * NS2 * SPAD;
    const uint32_t* GLp = g_GPL + (size_t)b * NS2 * SPAD;
    const uint32_t* aHp = g_aPH + (size_t)p * NS2 * NT;
    const uint32_t* aLp = g_aPL + (size_t)p * NS2 * NT;
    const float* au = g_a2u + (size_t)p * SPAD * NT;
    int cap = caps[c];
    int capN = (cap + 7) >> 3;
    int bsegs = 2 * capN;

    float w2acc[16] = {};

    int pb = 0;
    load_stage(smb, GHp, GLp, aHp, aLp, 0, 0, bsegs, tid);

    for (int st = 0; st < 3; ++st) {
        int s_base = st * 128;
        float acc[8][4] = {};
        for (int kc = 0; kc < 6; ++kc) {
            int gi = st * 6 + kc;
            if (gi < 17) {
                int nst = (kc < 5) ? st : st + 1;
                int nkc = (kc < 5) ? kc + 1 : 0;
                load_stage(smb + (uint32_t)(pb ^ 1) * ST_SIZE,
                           GHp, GLp, aHp, aLp, nkc * 32, nst * 128, bsegs, tid);
                CPA_WAIT1();
            } else {
                CPA_WAIT0();
            }
            __syncthreads();
            uint32_t* base = (uint32_t*)(smc + (uint32_t)pb * ST_SIZE);
            uint32_t* cth = base;
            uint32_t* ctl = base + 4224;
            uint32_t* ath = base + 8448;
            uint32_t* atl = base + 10624;
            int arow = wid * 16 + g;
#pragma unroll
            for (int j = 0; j < 4; ++j) {
                int jb = j * 8;
                int r0 = (jb + tg) * 132 + arow;
                int r1 = (jb + tg + 4) * 132 + arow;
                uint32_t ah0 = cth[r0], ah1 = cth[r0 + 8];
                uint32_t ah2 = cth[r1], ah3 = cth[r1 + 8];
                uint32_t al0 = ctl[r0], al1 = ctl[r0 + 8];
                uint32_t al2 = ctl[r1], al3 = ctl[r1 + 8];
#pragma unroll
                for (int nt = 0; nt < 8; ++nt) {
                    if (nt < capN) {
                        int b0i = (jb + tg) * 68 + nt * 8 + g;
                        int b1i = (jb + tg + 4) * 68 + nt * 8 + g;
                        uint32_t bh0 = ath[b0i], bh1 = ath[b1i];
                        uint32_t bl0 = atl[b0i], bl1 = atl[b1i];
                        mma16(acc[nt], ah0, ah1, ah2, ah3, bh0, bh1);
                        mma16(acc[nt], ah0, ah1, ah2, ah3, bl0, bl1);
                        mma16(acc[nt], al0, al1, al2, al3, bh0, bh1);
                    }
                }
            }
            __syncthreads();
            pb ^= 1;
        }
        // contraction (next stripe's loads in flight)
        int s0 = s_base + wid * 16 + g;
        int s1 = s0 + 8;
#pragma unroll
        for (int nt = 0; nt < 8; ++nt) {
            int col = nt * 8 + 2 * tg;
            float2 a0v = *(const float2*)&au[(size_t)s0 * NT + col];
            float2 a1v = *(const float2*)&au[(size_t)s1 * NT + col];
            w2acc[nt * 2 + 0] += a0v.x * acc[nt][0] + a1v.x * acc[nt][2];
            w2acc[nt * 2 + 1] += a0v.y * acc[nt][1] + a1v.y * acc[nt][3];
        }
    }
#pragma unroll
    for (int i = 0; i < 16; ++i) {
        float v = w2acc[i];
        v += __shfl_xor_sync(0xffffffffu, v, 4);
        v += __shfl_xor_sync(0xffffffffu, v, 8);
        v += __shfl_xor_sync(0xffffffffu, v, 16);
        w2acc[i] = v;
    }
    __syncthreads();
    if (g == 0) {
#pragma unroll
        for (int i = 0; i < 16; ++i) {
            int col = (i >> 1) * 8 + 2 * tg + (i & 1);
            w2red[wid * 64 + col] = w2acc[i];
        }
    }
    __syncthreads();
    if (tid < 64) {
        float s = 0.f;
#pragma unroll
        for (int w = 0; w < 8; ++w) s += w2red[w * 64 + tid];
        g_w2[p * 64 + tid] = s;
    }
}

// ================= finalizers =================
__global__ void csim_kernel(const int* __restrict__ caps) {
    int p = blockIdx.x, b = p % NB, c = p / NB;
    int t = threadIdx.x;
    float cs = g_cols[p * 64 + t];
    float ci = 1.f / cs;
    float w12 = g_w12[p * 64 + t] * ci;
    float w2 = ci * sqrtf(fmaxf(g_w2[p * 64 + t], 0.f));
    float w1 = g_w1n[c * 64 + t];
    float sim = w12 / fmaxf(w1 * w2, EPSV);
    float row = (t < caps[c]) ? __expf(TEMP2 * sim) : 0.f;
#pragma unroll
    for (int o = 16; o; o >>= 1) row += __shfl_xor_sync(0xffffffffu, row, o);
    __shared__ float sred[2];
    if ((t & 31) == 0) sred[t >> 5] = row;
    __syncthreads();
    if (t == 0) g_sims[b * NB + c] = TEMP3 * logf(sred[0] + sred[1]);
}

__global__ void att_kernel(float* __restrict__ ao) {
    int b = blockIdx.x;
    int p = b * NB + b;
    int tid = threadIdx.x;
    __shared__ float ci[64];
    if (tid < 64) ci[tid] = 1.f / g_cols[p * 64 + tid];
    __syncthreads();
    const float* au = g_a2u + (size_t)p * SPAD * NT;
    for (int i = tid; i < NS * NT; i += 256) {
        int s = i >> 6, t = i & 63;
        ao[((size_t)b * NT + t) * NS + s] = au[(size_t)s * NT + t] * ci[t];
    }
}

__global__ void loss_kernel(float* __restrict__ out) {
    __shared__ float part[4][NB];
    int i = threadIdx.x;
    if (i < NB) {
        const float* Ms = g_sims;
        const float* Mg = g_sc0;
        float m, sum;
        m = -INFINITY;
        for (int j = 0; j < NB; ++j) m = fmaxf(m, Ms[i * NB + j]);
        sum = 0.f;
        for (int j = 0; j < NB; ++j) sum += expf(Ms[i * NB + j] - m);
        part[0][i] = m + logf(sum) - Ms[i * NB + i];
        m = -INFINITY;
        for (int j = 0; j < NB; ++j) m = fmaxf(m, Ms[j * NB + i]);
        sum = 0.f;
        for (int j = 0; j < NB; ++j) sum += expf(Ms[j * NB + i] - m);
        part[1][i] = m + logf(sum) - Ms[i * NB + i];
        m = -INFINITY;
        for (int j = 0; j < NB; ++j) m = fmaxf(m, Mg[i * NB + j]);
        sum = 0.f;
        for (int j = 0; j < NB; ++j) sum += expf(Mg[i * NB + j] - m);
        part[2][i] = m + logf(sum) - Mg[i * NB + i];
        m = -INFINITY;
        for (int j = 0; j < NB; ++j) m = fmaxf(m, Mg[j * NB + i]);
        sum = 0.f;
        for (int j = 0; j < NB; ++j) sum += expf(Mg[j * NB + i] - m);
        part[3][i] = m + logf(sum) - Mg[i * NB + i];
    }
    __syncthreads();
    if (i == 0) {
        float l = 0.f;
        for (int k = 0; k < 4; ++k) {
            float s = 0.f;
            for (int j = 0; j < NB; ++j) s += part[k][j];
            l += s * (1.f / (float)NB);
        }
        out[0] = l;
    }
}

// ================= launch =================
extern "C" void kernel_launch(void* const* d_in, const int* in_sizes, int n_in,
                              void* d_out, int out_size) {
    const float* gfeat  = (const float*)d_in[0];
    const float* localf = (const float*)d_in[1];
    const float* words  = (const float*)d_in[2];
    const float* sfeat  = (const float*)d_in[3];
    const int*   caps   = (const int*)d_in[4];
    float* out = (float*)d_out;

    cudaFuncSetAttribute(scoreA_kernel, cudaFuncAttributeMaxDynamicSharedMemorySize, A_SMEM);
    cudaFuncSetAttribute(w2B_kernel, cudaFuncAttributeMaxDynamicSharedMemorySize, B_SMEM);

    size_t n_pad = (size_t)NB * NC * SPAD;
    pad_kernel<<<(unsigned)((n_pad + 255) / 256), 256>>>(localf);
    gram_kernel<<<dim3(6, NB), 256>>>();
    prep_GP<<<(unsigned)(((size_t)NB * NS2 * SPAD + 255) / 256), 256>>>();
    prep_ctxP<<<(unsigned)(((size_t)NB * ND2 * SPAD + 255) / 256), 256>>>(localf);
    prep_wP<<<(unsigned)(((size_t)NB * ND2 * NT + 255) / 256), 256>>>(words);

    // pair kernels early so the ncu -s window lands on them
    scoreA_kernel<<<NPAIR, 256, A_SMEM>>>(caps);
    prep_aP<<<(unsigned)(((size_t)NPAIR * NS2 * NT + 255) / 256), 256>>>();
    w2B_kernel<<<NPAIR, 256, B_SMEM>>>(caps);

    norms_kernel<<<NB, 64>>>(words, gfeat, sfeat);
    gscore_kernel<<<NB, 256>>>(gfeat, sfeat);
    csim_kernel<<<NPAIR, 64>>>(caps);

    int wa = (out_size >= 1 + NB * NT * NS) ? 1 : 0;
    if (wa) att_kernel<<<NB, 256>>>(out + 1);
    loss_kernel<<<1, 64>>>(out);
}